// round 13
// baseline (speedup 1.0000x reference)
#include <cuda_runtime.h>
#include <cuda_bf16.h>
#include <cstdint>
#include <math.h>

#define T_TOK 2048
#define D_DIM 1152
#define H_NUM 16
#define DH 72
#define NCU 9
#define TD (T_TOK * D_DIM)

// ---------------- scratch (no allocations allowed) ----------------
// g_part slots: 0,1=q halves; 2,3=k; 4,5=v; 6,7=o-proj partials
__device__ float g_part[8][TD];
__device__ float g_attn[TD];
__device__ float g_hsr[TD];                     // tf32-rounded hidden_states
__device__ float g_wr[4][D_DIM * D_DIM];        // tf32-rounded Wq,Wk,Wv,Wo

__device__ __forceinline__ float to_tf32(float x) {
    float y; asm("cvt.rna.tf32.f32 %0, %1;" : "=f"(y) : "f"(x)); return y;
}

__device__ __forceinline__ uint32_t smem_u32(const void* p) {
    uint32_t a;
    asm("{ .reg .u64 t; cvta.to.shared.u64 t, %1; cvt.u32.u64 %0, t; }" : "=r"(a) : "l"(p));
    return a;
}
__device__ __forceinline__ void cp16(uint32_t s, const void* g) {
    asm volatile("cp.async.ca.shared.global [%0], [%1], 16;" :: "r"(s), "l"(g));
}
#define CP_COMMIT() asm volatile("cp.async.commit_group;" ::: "memory")
#define CP_WAIT(n)  asm volatile("cp.async.wait_group %0;" :: "n"(n) : "memory")

__device__ __forceinline__ void mma_tf32(float& d0, float& d1, float& d2, float& d3,
                                         uint32_t a0, uint32_t a1, uint32_t a2, uint32_t a3,
                                         uint32_t b0, uint32_t b1) {
    asm volatile(
        "mma.sync.aligned.m16n8k8.row.col.f32.tf32.tf32.f32 "
        "{%0,%1,%2,%3}, {%4,%5,%6,%7}, {%8,%9}, {%0,%1,%2,%3};"
        : "+f"(d0), "+f"(d1), "+f"(d2), "+f"(d3)
        : "r"(a0), "r"(a1), "r"(a2), "r"(a3), "r"(b0), "r"(b1));
}

// ---------------- pre-round pass: tf32-round hs + 4 weights ----------------
__global__ void round_tf32_kernel(const float* __restrict__ hs,
                                  const float* __restrict__ wq, const float* __restrict__ wk,
                                  const float* __restrict__ wv, const float* __restrict__ wo)
{
    const int seg = blockIdx.y;
    const float* src;
    float* dst;
    int n4;
    if (seg == 0) { src = hs; dst = g_hsr;   n4 = TD / 4; }
    else {
        const float* ws[4] = {wq, wk, wv, wo};
        src = ws[seg - 1]; dst = g_wr[seg - 1]; n4 = D_DIM * D_DIM / 4;
    }
    int idx = blockIdx.x * blockDim.x + threadIdx.x;
    if (idx >= n4) return;
    float4 v = ((const float4*)src)[idx];
    v.x = to_tf32(v.x); v.y = to_tf32(v.y); v.z = to_tf32(v.z); v.w = to_tf32(v.w);
    ((float4*)dst)[idx] = v;
}

// ============ cp.async 3-stage split-K tf32 GEMM: Cpart = A @ W^T (half K) ============
// blockIdx.z: proj = z>>1, half = z&1 (K offset half*576). No bias here.
#define KCH 16
#define KHALF 576
#define NCHUNK_H (KHALF / KCH)   // 36
#define SPAD 20
#define STAGES 3
#define STG_FLOATS (128 * SPAD)
#define GEMM_SMEM (STAGES * 2 * STG_FLOATS * 4)   // 61440 bytes

__global__ __launch_bounds__(256, 2) void gemm_cp_tf32(
    const float* __restrict__ A,
    const float* __restrict__ W0, const float* __restrict__ W1, const float* __restrict__ W2,
    float* __restrict__ Cbase)
{
    extern __shared__ float smemf[];
    float* sA = smemf;
    float* sB = smemf + STAGES * STG_FLOATS;
    const uint32_t uAaddr = smem_u32(sA);
    const uint32_t uBaddr = smem_u32(sB);

    const int z = blockIdx.z;
    const int proj = z >> 1;
    const int koff = (z & 1) * KHALF;
    const float* Bw = (proj == 0) ? W0 : (proj == 1) ? W1 : W2;
    float* C = Cbase + (size_t)z * TD;

    const int tid = threadIdx.x;
    const int wid = tid >> 5;
    const int lane = tid & 31;
    const int gid = lane >> 2;
    const int tig = lane & 3;
    const int wm = wid >> 2;
    const int wn = wid & 3;

    const int bm = blockIdx.y * 128;
    const int bn = blockIdx.x * 128;

    auto issue = [&](int c, int stg) {
#pragma unroll
        for (int i = 0; i < 2; i++) {
            int idx = tid * 2 + i;
            int row = idx >> 2;
            int c4 = (idx & 3) * 4;
            uint32_t off = (uint32_t)(stg * STG_FLOATS + row * SPAD + c4) * 4u;
            cp16(uAaddr + off, A  + (size_t)(bm + row) * D_DIM + koff + c * KCH + c4);
            cp16(uBaddr + off, Bw + (size_t)(bn + row) * D_DIM + koff + c * KCH + c4);
        }
    };

    float acc[4][4][4];
#pragma unroll
    for (int i = 0; i < 4; i++)
#pragma unroll
        for (int j = 0; j < 4; j++)
#pragma unroll
            for (int r = 0; r < 4; r++) acc[i][j][r] = 0.f;

    // prologue: 2 stages in flight
    issue(0, 0); CP_COMMIT();
    issue(1, 1); CP_COMMIT();

    int stg = 0;                 // stage being computed
    int wstg = STAGES - 1;       // stage being written next
    for (int c = 0; c < NCHUNK_H; c++) {
        CP_WAIT(1);
        __syncthreads();

        const uint32_t* uA = (const uint32_t*)(sA + stg * STG_FLOATS);
        const uint32_t* uB = (const uint32_t*)(sB + stg * STG_FLOATS);

#pragma unroll
        for (int ks = 0; ks < 2; ks++) {
            const int k0 = ks * 8;
            uint32_t af[4][4], bf[4][2];
#pragma unroll
            for (int ma = 0; ma < 4; ma++) {
                int r0 = (wm * 64 + ma * 16 + gid) * SPAD;
                af[ma][0] = uA[r0 + k0 + tig];
                af[ma][1] = uA[r0 + 8 * SPAD + k0 + tig];
                af[ma][2] = uA[r0 + k0 + tig + 4];
                af[ma][3] = uA[r0 + 8 * SPAD + k0 + tig + 4];
            }
#pragma unroll
            for (int na = 0; na < 4; na++) {
                int r0 = (wn * 32 + na * 8 + gid) * SPAD;
                bf[na][0] = uB[r0 + k0 + tig];
                bf[na][1] = uB[r0 + k0 + tig + 4];
            }
#pragma unroll
            for (int ma = 0; ma < 4; ma++)
#pragma unroll
                for (int na = 0; na < 4; na++)
                    mma_tf32(acc[ma][na][0], acc[ma][na][1], acc[ma][na][2], acc[ma][na][3],
                             af[ma][0], af[ma][1], af[ma][2], af[ma][3],
                             bf[na][0], bf[na][1]);
        }

        if (c + 2 < NCHUNK_H) issue(c + 2, wstg);
        CP_COMMIT();
        if (++stg == STAGES) stg = 0;
        if (++wstg == STAGES) wstg = 0;
    }

#pragma unroll
    for (int ma = 0; ma < 4; ma++) {
        int row = bm + wm * 64 + ma * 16 + gid;
#pragma unroll
        for (int na = 0; na < 4; na++) {
            int col = bn + wn * 32 + na * 8 + tig * 2;
            *(float2*)(C + (size_t)row * D_DIM + col) = make_float2(acc[ma][na][0], acc[ma][na][1]);
            *(float2*)(C + (size_t)(row + 8) * D_DIM + col) = make_float2(acc[ma][na][2], acc[ma][na][3]);
        }
    }
}

// ---------------- O-projection reduction: out = p6 + p7 + bo ----------------
__global__ void reduce_out_kernel(const float* __restrict__ p0, const float* __restrict__ p1,
                                  const float* __restrict__ bo, float* __restrict__ out)
{
    int idx = blockIdx.x * blockDim.x + threadIdx.x;
    if (idx >= TD / 4) return;
    int col = (idx * 4) % D_DIM;
    float4 a = ((const float4*)p0)[idx];
    float4 b = ((const float4*)p1)[idx];
    float4 bb = *(const float4*)(bo + col);
    float4 o;
    o.x = a.x + b.x + bb.x;
    o.y = a.y + b.y + bb.y;
    o.z = a.z + b.z + bb.z;
    o.w = a.w + b.w + bb.w;
    ((float4*)out)[idx] = o;
}

// ---------------- Segment-masked flash attention (tf32 mma.sync, fused RoPE + QKV reduce) ----------------
// grid (T/128, H), 256 threads (8 warps x 16 query rows). K-tile 64.
#define QT 128
#define KT 64
#define QK_STRIDE 76
#define V_STRIDE 72
#define P_STRIDE 68
#define ATTN_SMEM ((QT * QK_STRIDE + KT * QK_STRIDE + KT * V_STRIDE + QT * P_STRIDE) * 4)

__global__ __launch_bounds__(256) void attn_kernel(
    const float* __restrict__ pq0, const float* __restrict__ pq1,
    const float* __restrict__ pk0, const float* __restrict__ pk1,
    const float* __restrict__ pv0, const float* __restrict__ pv1,
    const float* __restrict__ bq, const float* __restrict__ bk, const float* __restrict__ bv,
    const int* __restrict__ cu,
    const float* __restrict__ cosp, const float* __restrict__ sinp,
    float* __restrict__ out)
{
    extern __shared__ float smemf[];
    float* sQ = smemf;                            // 128 x 76
    float* sK = sQ + QT * QK_STRIDE;              // 64 x 76
    float* sV = sK + KT * QK_STRIDE;              // 64 x 72
    float* sP = sV + KT * V_STRIDE;               // 128 x 68
    __shared__ int sCu[NCU];
    __shared__ int sSegQ[QT];
    __shared__ int sSegK[KT];

    const int tid = threadIdx.x;
    const int wid = tid >> 5;
    const int lane = tid & 31;
    const int gid = lane >> 2;
    const int tig = lane & 3;
    const int h = blockIdx.y;
    const int q0 = blockIdx.x * QT;

    if (tid < NCU) sCu[tid] = cu[tid];
    __syncthreads();

    const float scale = rsqrtf((float)DH);

    // ---- load Q: sum split-K partials + bias, fused RoPE, scale, round ----
    for (int i = tid; i < QT * 9; i += 256) {
        int r = i / 9, c4 = (i % 9) * 4;
        int t = q0 + r;
        size_t base = (size_t)t * D_DIM + h * DH;
        float4 a1 = *(const float4*)(pq0 + base + c4);
        float4 b1 = *(const float4*)(pq1 + base + c4);
        float4 a2 = *(const float4*)(pq0 + base + c4 + 36);
        float4 b2 = *(const float4*)(pq1 + base + c4 + 36);
        float4 g1 = *(const float4*)(bq + h * DH + c4);
        float4 g2 = *(const float4*)(bq + h * DH + c4 + 36);
        float4 x1, x2;
        x1.x = a1.x + b1.x + g1.x; x1.y = a1.y + b1.y + g1.y;
        x1.z = a1.z + b1.z + g1.z; x1.w = a1.w + b1.w + g1.w;
        x2.x = a2.x + b2.x + g2.x; x2.y = a2.y + b2.y + g2.y;
        x2.z = a2.z + b2.z + g2.z; x2.w = a2.w + b2.w + g2.w;
        float4 cc = *(const float4*)(cosp + (size_t)t * DH + c4);
        float4 ss = *(const float4*)(sinp + (size_t)t * DH + c4);
        float4 o1, o2;
        o1.x = to_tf32((x1.x * cc.x - x2.x * ss.x) * scale);
        o1.y = to_tf32((x1.y * cc.y - x2.y * ss.y) * scale);
        o1.z = to_tf32((x1.z * cc.z - x2.z * ss.z) * scale);
        o1.w = to_tf32((x1.w * cc.w - x2.w * ss.w) * scale);
        o2.x = to_tf32((x2.x * cc.x + x1.x * ss.x) * scale);
        o2.y = to_tf32((x2.y * cc.y + x1.y * ss.y) * scale);
        o2.z = to_tf32((x2.z * cc.z + x1.z * ss.z) * scale);
        o2.w = to_tf32((x2.w * cc.w + x1.w * ss.w) * scale);
        *(float4*)(&sQ[r * QK_STRIDE + c4]) = o1;
        *(float4*)(&sQ[r * QK_STRIDE + c4 + 36]) = o2;
    }
    if (tid < QT) {
        int t = q0 + tid;
        int s = 0;
#pragma unroll
        for (int j = 1; j < NCU; j++)
            if (sCu[j] <= t) s = j;
        sSegQ[tid] = s;
    }
    __syncthreads();

    const int seg_lo = sSegQ[0];
    const int seg_hi = sSegQ[QT - 1];
    const int k_end = sCu[seg_hi + 1];
    const int kc0 = (sCu[seg_lo] / KT) * KT;

    const int r0 = wid * 16 + gid;
    const int segq0 = sSegQ[r0];
    const int segq1 = sSegQ[r0 + 8];

    float m0 = -1e30f, m1 = -1e30f, l0 = 0.f, l1 = 0.f;
    float O[9][4];
#pragma unroll
    for (int no = 0; no < 9; no++)
#pragma unroll
        for (int r = 0; r < 4; r++) O[no][r] = 0.f;

    const uint32_t* uQ = (const uint32_t*)sQ;
    const uint32_t* uK = (const uint32_t*)sK;
    const uint32_t* uV = (const uint32_t*)sV;
    const uint32_t* uP = (const uint32_t*)sP;

    for (int kc = kc0; kc < k_end; kc += KT) {
        // ---- load K: partial sum + bias + RoPE ----
        for (int i = tid; i < KT * 9; i += 256) {
            int r = i / 9, c4 = (i % 9) * 4;
            int t = kc + r;
            size_t base = (size_t)t * D_DIM + h * DH;
            float4 a1 = *(const float4*)(pk0 + base + c4);
            float4 b1 = *(const float4*)(pk1 + base + c4);
            float4 a2 = *(const float4*)(pk0 + base + c4 + 36);
            float4 b2 = *(const float4*)(pk1 + base + c4 + 36);
            float4 g1 = *(const float4*)(bk + h * DH + c4);
            float4 g2 = *(const float4*)(bk + h * DH + c4 + 36);
            float4 x1, x2;
            x1.x = a1.x + b1.x + g1.x; x1.y = a1.y + b1.y + g1.y;
            x1.z = a1.z + b1.z + g1.z; x1.w = a1.w + b1.w + g1.w;
            x2.x = a2.x + b2.x + g2.x; x2.y = a2.y + b2.y + g2.y;
            x2.z = a2.z + b2.z + g2.z; x2.w = a2.w + b2.w + g2.w;
            float4 cc = *(const float4*)(cosp + (size_t)t * DH + c4);
            float4 ss = *(const float4*)(sinp + (size_t)t * DH + c4);
            float4 o1, o2;
            o1.x = to_tf32(x1.x * cc.x - x2.x * ss.x);
            o1.y = to_tf32(x1.y * cc.y - x2.y * ss.y);
            o1.z = to_tf32(x1.z * cc.z - x2.z * ss.z);
            o1.w = to_tf32(x1.w * cc.w - x2.w * ss.w);
            o2.x = to_tf32(x2.x * cc.x + x1.x * ss.x);
            o2.y = to_tf32(x2.y * cc.y + x1.y * ss.y);
            o2.z = to_tf32(x2.z * cc.z + x1.z * ss.z);
            o2.w = to_tf32(x2.w * cc.w + x1.w * ss.w);
            *(float4*)(&sK[r * QK_STRIDE + c4]) = o1;
            *(float4*)(&sK[r * QK_STRIDE + c4 + 36]) = o2;
        }
        // ---- load V: partial sum + bias ----
        for (int i = tid; i < KT * (DH / 4); i += 256) {
            int r = i / (DH / 4), c4 = (i % (DH / 4)) * 4;
            size_t base = (size_t)(kc + r) * D_DIM + h * DH + c4;
            float4 a = *(const float4*)(pv0 + base);
            float4 b = *(const float4*)(pv1 + base);
            float4 g = *(const float4*)(bv + h * DH + c4);
            float4 vv;
            vv.x = to_tf32(a.x + b.x + g.x);
            vv.y = to_tf32(a.y + b.y + g.y);
            vv.z = to_tf32(a.z + b.z + g.z);
            vv.w = to_tf32(a.w + b.w + g.w);
            *(float4*)(&sV[r * V_STRIDE + c4]) = vv;
        }
        if (tid < KT) {
            int t = kc + tid;
            int s = 0;
#pragma unroll
            for (int j = 1; j < NCU; j++)
                if (sCu[j] <= t) s = j;
            sSegK[tid] = s;
        }
        __syncthreads();

        // ---- S = Q K^T ----
        float accS[8][4];
#pragma unroll
        for (int na = 0; na < 8; na++)
#pragma unroll
            for (int r = 0; r < 4; r++) accS[na][r] = 0.f;

#pragma unroll
        for (int ks = 0; ks < 9; ks++) {
            const int k0 = ks * 8;
            uint32_t a0 = uQ[r0 * QK_STRIDE + k0 + tig];
            uint32_t a1 = uQ[(r0 + 8) * QK_STRIDE + k0 + tig];
            uint32_t a2 = uQ[r0 * QK_STRIDE + k0 + tig + 4];
            uint32_t a3 = uQ[(r0 + 8) * QK_STRIDE + k0 + tig + 4];
#pragma unroll
            for (int na = 0; na < 8; na++) {
                uint32_t b0 = uK[(na * 8 + gid) * QK_STRIDE + k0 + tig];
                uint32_t b1 = uK[(na * 8 + gid) * QK_STRIDE + k0 + tig + 4];
                mma_tf32(accS[na][0], accS[na][1], accS[na][2], accS[na][3],
                         a0, a1, a2, a3, b0, b1);
            }
        }

        // ---- mask ----
#pragma unroll
        for (int na = 0; na < 8; na++) {
            int c0 = na * 8 + tig * 2;
            int sk0 = sSegK[c0], sk1 = sSegK[c0 + 1];
            if (sk0 != segq0) accS[na][0] = -1e30f;
            if (sk1 != segq0) accS[na][1] = -1e30f;
            if (sk0 != segq1) accS[na][2] = -1e30f;
            if (sk1 != segq1) accS[na][3] = -1e30f;
        }

        // ---- online softmax ----
        float mt0 = -1e30f, mt1 = -1e30f;
#pragma unroll
        for (int na = 0; na < 8; na++) {
            mt0 = fmaxf(mt0, fmaxf(accS[na][0], accS[na][1]));
            mt1 = fmaxf(mt1, fmaxf(accS[na][2], accS[na][3]));
        }
        mt0 = fmaxf(mt0, __shfl_xor_sync(0xffffffffu, mt0, 1));
        mt0 = fmaxf(mt0, __shfl_xor_sync(0xffffffffu, mt0, 2));
        mt1 = fmaxf(mt1, __shfl_xor_sync(0xffffffffu, mt1, 1));
        mt1 = fmaxf(mt1, __shfl_xor_sync(0xffffffffu, mt1, 2));
        float mn0 = fmaxf(m0, mt0);
        float mn1 = fmaxf(m1, mt1);

        float ls0 = 0.f, ls1 = 0.f;
#pragma unroll
        for (int na = 0; na < 8; na++) {
            float p00 = (accS[na][0] < -1e29f) ? 0.f : to_tf32(__expf(accS[na][0] - mn0));
            float p01 = (accS[na][1] < -1e29f) ? 0.f : to_tf32(__expf(accS[na][1] - mn0));
            float p10 = (accS[na][2] < -1e29f) ? 0.f : to_tf32(__expf(accS[na][2] - mn1));
            float p11 = (accS[na][3] < -1e29f) ? 0.f : to_tf32(__expf(accS[na][3] - mn1));
            ls0 += p00 + p01;
            ls1 += p10 + p11;
            int c0 = na * 8 + tig * 2;
            *(float2*)(&sP[r0 * P_STRIDE + c0]) = make_float2(p00, p01);
            *(float2*)(&sP[(r0 + 8) * P_STRIDE + c0]) = make_float2(p10, p11);
        }
        ls0 += __shfl_xor_sync(0xffffffffu, ls0, 1);
        ls0 += __shfl_xor_sync(0xffffffffu, ls0, 2);
        ls1 += __shfl_xor_sync(0xffffffffu, ls1, 1);
        ls1 += __shfl_xor_sync(0xffffffffu, ls1, 2);

        float al0 = __expf(m0 - mn0);
        float al1 = __expf(m1 - mn1);
        l0 = l0 * al0 + ls0;
        l1 = l1 * al1 + ls1;
        m0 = mn0; m1 = mn1;

#pragma unroll
        for (int no = 0; no < 9; no++) {
            O[no][0] *= al0; O[no][1] *= al0;
            O[no][2] *= al1; O[no][3] *= al1;
        }
        __syncwarp();

        // ---- O += P V ----
#pragma unroll
        for (int ks = 0; ks < 8; ks++) {
            const int k0 = ks * 8;
            uint32_t a0 = uP[r0 * P_STRIDE + k0 + tig];
            uint32_t a1 = uP[(r0 + 8) * P_STRIDE + k0 + tig];
            uint32_t a2 = uP[r0 * P_STRIDE + k0 + tig + 4];
            uint32_t a3 = uP[(r0 + 8) * P_STRIDE + k0 + tig + 4];
#pragma unroll
            for (int no = 0; no < 9; no++) {
                uint32_t b0 = uV[(k0 + tig) * V_STRIDE + no * 8 + gid];
                uint32_t b1 = uV[(k0 + tig + 4) * V_STRIDE + no * 8 + gid];
                mma_tf32(O[no][0], O[no][1], O[no][2], O[no][3],
                         a0, a1, a2, a3, b0, b1);
            }
        }
        __syncthreads();
    }

    float il0 = 1.f / l0;
    float il1 = 1.f / l1;
    size_t ob0 = (size_t)(q0 + r0) * D_DIM + h * DH;
    size_t ob1 = (size_t)(q0 + r0 + 8) * D_DIM + h * DH;
#pragma unroll
    for (int no = 0; no < 9; no++) {
        int c0 = no * 8 + tig * 2;
        *(float2*)(out + ob0 + c0) = make_float2(to_tf32(O[no][0] * il0), to_tf32(O[no][1] * il0));
        *(float2*)(out + ob1 + c0) = make_float2(to_tf32(O[no][2] * il1), to_tf32(O[no][3] * il1));
    }
}

// ---------------- host launch ----------------
extern "C" void kernel_launch(void* const* d_in, const int* in_sizes, int n_in,
                              void* d_out, int out_size)
{
    const float* hs   = (const float*)d_in[0];
    const int*   cu   = (const int*)  d_in[1];
    const float* cosp = (const float*)d_in[2];
    const float* sinp = (const float*)d_in[3];
    const float* Wq   = (const float*)d_in[4];
    const float* bq   = (const float*)d_in[5];
    const float* Wk   = (const float*)d_in[6];
    const float* bk   = (const float*)d_in[7];
    const float* Wv   = (const float*)d_in[8];
    const float* bv   = (const float*)d_in[9];
    const float* Wo   = (const float*)d_in[10];
    const float* bo   = (const float*)d_in[11];
    float* out = (float*)d_out;

    float *part, *attn, *hsr, *wr;
    cudaGetSymbolAddress((void**)&part, g_part);
    cudaGetSymbolAddress((void**)&attn, g_attn);
    cudaGetSymbolAddress((void**)&hsr, g_hsr);
    cudaGetSymbolAddress((void**)&wr, g_wr);
    float* wqr = wr;
    float* wkr = wr + (size_t)D_DIM * D_DIM;
    float* wvr = wr + 2 * (size_t)D_DIM * D_DIM;
    float* wor = wr + 3 * (size_t)D_DIM * D_DIM;

    // pre-round hs + weights (grid x sized for the LARGEST segment: hs)
    int n4hs = TD / 4;
    dim3 rgrid((n4hs + 255) / 256, 5);
    round_tf32_kernel<<<rgrid, 256>>>(hs, Wq, Wk, Wv, Wo);

    cudaFuncSetAttribute(gemm_cp_tf32,
                         cudaFuncAttributeMaxDynamicSharedMemorySize, GEMM_SMEM);

    // fused QKV, split-K x2: z = proj*2 + half -> g_part slots 0..5
    dim3 qkv_grid(D_DIM / 128, T_TOK / 128, 6);
    gemm_cp_tf32<<<qkv_grid, 256, GEMM_SMEM>>>(hsr, wqr, wkr, wvr, part);

    // attention: fused RoPE + QKV partial-sum + bias
    cudaFuncSetAttribute(attn_kernel,
                         cudaFuncAttributeMaxDynamicSharedMemorySize, ATTN_SMEM);
    attn_kernel<<<dim3(T_TOK / QT, H_NUM), 256, ATTN_SMEM>>>(
        part + 0 * (size_t)TD, part + 1 * (size_t)TD,
        part + 2 * (size_t)TD, part + 3 * (size_t)TD,
        part + 4 * (size_t)TD, part + 5 * (size_t)TD,
        bq, bk, bv, cu, cosp, sinp, attn);

    // O projection, split-K x2 -> slots 6,7 (Cbase offset by 6*TD; z in {0,1})
    dim3 o_grid(D_DIM / 128, T_TOK / 128, 2);
    gemm_cp_tf32<<<o_grid, 256, GEMM_SMEM>>>(attn, wor, wor, wor, part + 6 * (size_t)TD);

    // final reduction: out = p6 + p7 + bo
    reduce_out_kernel<<<(TD / 4 + 255) / 256, 256>>>(
        part + 6 * (size_t)TD, part + 7 * (size_t)TD, bo, out);
}

// round 14
// speedup vs baseline: 1.1466x; 1.1466x over previous
#include <cuda_runtime.h>
#include <cuda_bf16.h>
#include <cstdint>
#include <math.h>

#define T_TOK 2048
#define D_DIM 1152
#define H_NUM 16
#define DH 72
#define NCU 9
#define TD (T_TOK * D_DIM)

// ---------------- scratch (no allocations allowed) ----------------
// g_part slots: 0,1=q halves; 2,3=k; 4,5=v; 6,7=o-proj partials
__device__ float g_part[8][TD];
__device__ float g_attn[TD];
__device__ float g_hsr[TD];                     // tf32-rounded hidden_states
__device__ float g_wr[4][D_DIM * D_DIM];        // tf32-rounded Wq,Wk,Wv,Wo

__device__ __forceinline__ float to_tf32(float x) {
    float y; asm("cvt.rna.tf32.f32 %0, %1;" : "=f"(y) : "f"(x)); return y;
}

__device__ __forceinline__ uint32_t smem_u32(const void* p) {
    uint32_t a;
    asm("{ .reg .u64 t; cvta.to.shared.u64 t, %1; cvt.u32.u64 %0, t; }" : "=r"(a) : "l"(p));
    return a;
}
__device__ __forceinline__ void cp16(uint32_t s, const void* g) {
    asm volatile("cp.async.ca.shared.global [%0], [%1], 16;" :: "r"(s), "l"(g));
}
#define CP_COMMIT() asm volatile("cp.async.commit_group;" ::: "memory")
#define CP_WAIT(n)  asm volatile("cp.async.wait_group %0;" :: "n"(n) : "memory")

__device__ __forceinline__ void mma_tf32(float& d0, float& d1, float& d2, float& d3,
                                         uint32_t a0, uint32_t a1, uint32_t a2, uint32_t a3,
                                         uint32_t b0, uint32_t b1) {
    asm volatile(
        "mma.sync.aligned.m16n8k8.row.col.f32.tf32.tf32.f32 "
        "{%0,%1,%2,%3}, {%4,%5,%6,%7}, {%8,%9}, {%0,%1,%2,%3};"
        : "+f"(d0), "+f"(d1), "+f"(d2), "+f"(d3)
        : "r"(a0), "r"(a1), "r"(a2), "r"(a3), "r"(b0), "r"(b1));
}

// ---------------- pre-round pass: tf32-round hs + 4 weights ----------------
__global__ void round_tf32_kernel(const float* __restrict__ hs,
                                  const float* __restrict__ wq, const float* __restrict__ wk,
                                  const float* __restrict__ wv, const float* __restrict__ wo)
{
    const int seg = blockIdx.y;
    const float* src;
    float* dst;
    int n4;
    if (seg == 0) { src = hs; dst = g_hsr;   n4 = TD / 4; }
    else {
        const float* ws[4] = {wq, wk, wv, wo};
        src = ws[seg - 1]; dst = g_wr[seg - 1]; n4 = D_DIM * D_DIM / 4;
    }
    int idx = blockIdx.x * blockDim.x + threadIdx.x;
    if (idx >= n4) return;
    float4 v = ((const float4*)src)[idx];
    v.x = to_tf32(v.x); v.y = to_tf32(v.y); v.z = to_tf32(v.z); v.w = to_tf32(v.w);
    ((float4*)dst)[idx] = v;
}

// ============ cp.async 3-stage split-K tf32 GEMM: Cpart = A @ W^T (half K) ============
// CTA tile 256x128, 8 warps in 4x2 layout, warp tile 64x64 (m=4, n=8 atoms).
// blockIdx.z: proj = z>>1, half = z&1 (K offset half*576). No bias here.
#define BM 256
#define BN 128
#define KCH 16
#define KHALF 576
#define NCHUNK_H (KHALF / KCH)   // 36
#define SPAD 20
#define STAGES 3
#define A_STG (BM * SPAD)        // 5120 floats
#define B_STG (BN * SPAD)        // 2560 floats
#define GEMM_SMEM (STAGES * (A_STG + B_STG) * 4)   // 92160 bytes

__global__ __launch_bounds__(256) void gemm_cp_tf32(
    const float* __restrict__ A,
    const float* __restrict__ W0, const float* __restrict__ W1, const float* __restrict__ W2,
    float* __restrict__ Cbase)
{
    extern __shared__ float smemf[];
    float* sA = smemf;
    float* sB = smemf + STAGES * A_STG;
    const uint32_t uAaddr = smem_u32(sA);
    const uint32_t uBaddr = smem_u32(sB);

    const int z = blockIdx.z;
    const int proj = z >> 1;
    const int koff = (z & 1) * KHALF;
    const float* Bw = (proj == 0) ? W0 : (proj == 1) ? W1 : W2;
    float* C = Cbase + (size_t)z * TD;

    const int tid = threadIdx.x;
    const int wid = tid >> 5;
    const int lane = tid & 31;
    const int gid = lane >> 2;
    const int tig = lane & 3;
    const int wm = wid & 3;      // 0..3 (64-row slab)
    const int wn = wid >> 2;     // 0..1 (64-col slab)

    const int bm = blockIdx.y * BM;
    const int bn = blockIdx.x * BN;

    auto issue = [&](int c, int stg) {
        // A: 1024 float4 (256 rows x 4), 4 per thread; coalesced 4-thread rows
#pragma unroll
        for (int i = 0; i < 4; i++) {
            int idx = i * 256 + tid;
            int row = idx >> 2;
            int c4 = (idx & 3) * 4;
            uint32_t off = (uint32_t)(stg * A_STG + row * SPAD + c4) * 4u;
            cp16(uAaddr + off, A + (size_t)(bm + row) * D_DIM + koff + c * KCH + c4);
        }
        // B: 512 float4 (128 rows x 4), 2 per thread
#pragma unroll
        for (int i = 0; i < 2; i++) {
            int idx = i * 256 + tid;
            int row = idx >> 2;
            int c4 = (idx & 3) * 4;
            uint32_t off = (uint32_t)(stg * B_STG + row * SPAD + c4) * 4u;
            cp16(uBaddr + off, Bw + (size_t)(bn + row) * D_DIM + koff + c * KCH + c4);
        }
    };

    float acc[4][8][4];
#pragma unroll
    for (int i = 0; i < 4; i++)
#pragma unroll
        for (int j = 0; j < 8; j++)
#pragma unroll
            for (int r = 0; r < 4; r++) acc[i][j][r] = 0.f;

    // prologue: 2 stages in flight
    issue(0, 0); CP_COMMIT();
    issue(1, 1); CP_COMMIT();

    int stg = 0;                 // stage being computed
    int wstg = STAGES - 1;       // stage being written next
    for (int c = 0; c < NCHUNK_H; c++) {
        CP_WAIT(1);
        __syncthreads();

        const uint32_t* uA = (const uint32_t*)(sA + stg * A_STG);
        const uint32_t* uB = (const uint32_t*)(sB + stg * B_STG);

#pragma unroll
        for (int ks = 0; ks < 2; ks++) {
            const int k0 = ks * 8;
            uint32_t af[4][4], bf[8][2];
#pragma unroll
            for (int ma = 0; ma < 4; ma++) {
                int r0 = (wm * 64 + ma * 16 + gid) * SPAD;
                af[ma][0] = uA[r0 + k0 + tig];
                af[ma][1] = uA[r0 + 8 * SPAD + k0 + tig];
                af[ma][2] = uA[r0 + k0 + tig + 4];
                af[ma][3] = uA[r0 + 8 * SPAD + k0 + tig + 4];
            }
#pragma unroll
            for (int na = 0; na < 8; na++) {
                int r0 = (wn * 64 + na * 8 + gid) * SPAD;
                bf[na][0] = uB[r0 + k0 + tig];
                bf[na][1] = uB[r0 + k0 + tig + 4];
            }
#pragma unroll
            for (int ma = 0; ma < 4; ma++)
#pragma unroll
                for (int na = 0; na < 8; na++)
                    mma_tf32(acc[ma][na][0], acc[ma][na][1], acc[ma][na][2], acc[ma][na][3],
                             af[ma][0], af[ma][1], af[ma][2], af[ma][3],
                             bf[na][0], bf[na][1]);
        }

        if (c + 2 < NCHUNK_H) issue(c + 2, wstg);
        CP_COMMIT();
        if (++stg == STAGES) stg = 0;
        if (++wstg == STAGES) wstg = 0;
    }

#pragma unroll
    for (int ma = 0; ma < 4; ma++) {
        int row = bm + wm * 64 + ma * 16 + gid;
#pragma unroll
        for (int na = 0; na < 8; na++) {
            int col = bn + wn * 64 + na * 8 + tig * 2;
            *(float2*)(C + (size_t)row * D_DIM + col) = make_float2(acc[ma][na][0], acc[ma][na][1]);
            *(float2*)(C + (size_t)(row + 8) * D_DIM + col) = make_float2(acc[ma][na][2], acc[ma][na][3]);
        }
    }
}

// ---------------- O-projection reduction: out = p6 + p7 + bo ----------------
__global__ void reduce_out_kernel(const float* __restrict__ p0, const float* __restrict__ p1,
                                  const float* __restrict__ bo, float* __restrict__ out)
{
    int idx = blockIdx.x * blockDim.x + threadIdx.x;
    if (idx >= TD / 4) return;
    int col = (idx * 4) % D_DIM;
    float4 a = ((const float4*)p0)[idx];
    float4 b = ((const float4*)p1)[idx];
    float4 bb = *(const float4*)(bo + col);
    float4 o;
    o.x = a.x + b.x + bb.x;
    o.y = a.y + b.y + bb.y;
    o.z = a.z + b.z + bb.z;
    o.w = a.w + b.w + bb.w;
    ((float4*)out)[idx] = o;
}

// ---------------- Segment-masked flash attention (tf32 mma.sync, fused RoPE + QKV reduce) ----------------
// grid (T/128, H), 256 threads (8 warps x 16 query rows). K-tile 64.
#define QT 128
#define KT 64
#define QK_STRIDE 76
#define V_STRIDE 72
#define P_STRIDE 68
#define ATTN_SMEM ((QT * QK_STRIDE + KT * QK_STRIDE + KT * V_STRIDE + QT * P_STRIDE) * 4)

__global__ __launch_bounds__(256) void attn_kernel(
    const float* __restrict__ pq0, const float* __restrict__ pq1,
    const float* __restrict__ pk0, const float* __restrict__ pk1,
    const float* __restrict__ pv0, const float* __restrict__ pv1,
    const float* __restrict__ bq, const float* __restrict__ bk, const float* __restrict__ bv,
    const int* __restrict__ cu,
    const float* __restrict__ cosp, const float* __restrict__ sinp,
    float* __restrict__ out)
{
    extern __shared__ float smemf[];
    float* sQ = smemf;                            // 128 x 76
    float* sK = sQ + QT * QK_STRIDE;              // 64 x 76
    float* sV = sK + KT * QK_STRIDE;              // 64 x 72
    float* sP = sV + KT * V_STRIDE;               // 128 x 68
    __shared__ int sCu[NCU];
    __shared__ int sSegQ[QT];
    __shared__ int sSegK[KT];

    const int tid = threadIdx.x;
    const int wid = tid >> 5;
    const int lane = tid & 31;
    const int gid = lane >> 2;
    const int tig = lane & 3;
    const int h = blockIdx.y;
    const int q0 = blockIdx.x * QT;

    if (tid < NCU) sCu[tid] = cu[tid];
    __syncthreads();

    const float scale = rsqrtf((float)DH);

    // ---- load Q: sum split-K partials + bias, fused RoPE, scale, round ----
    for (int i = tid; i < QT * 9; i += 256) {
        int r = i / 9, c4 = (i % 9) * 4;
        int t = q0 + r;
        size_t base = (size_t)t * D_DIM + h * DH;
        float4 a1 = *(const float4*)(pq0 + base + c4);
        float4 b1 = *(const float4*)(pq1 + base + c4);
        float4 a2 = *(const float4*)(pq0 + base + c4 + 36);
        float4 b2 = *(const float4*)(pq1 + base + c4 + 36);
        float4 g1 = *(const float4*)(bq + h * DH + c4);
        float4 g2 = *(const float4*)(bq + h * DH + c4 + 36);
        float4 x1, x2;
        x1.x = a1.x + b1.x + g1.x; x1.y = a1.y + b1.y + g1.y;
        x1.z = a1.z + b1.z + g1.z; x1.w = a1.w + b1.w + g1.w;
        x2.x = a2.x + b2.x + g2.x; x2.y = a2.y + b2.y + g2.y;
        x2.z = a2.z + b2.z + g2.z; x2.w = a2.w + b2.w + g2.w;
        float4 cc = *(const float4*)(cosp + (size_t)t * DH + c4);
        float4 ss = *(const float4*)(sinp + (size_t)t * DH + c4);
        float4 o1, o2;
        o1.x = to_tf32((x1.x * cc.x - x2.x * ss.x) * scale);
        o1.y = to_tf32((x1.y * cc.y - x2.y * ss.y) * scale);
        o1.z = to_tf32((x1.z * cc.z - x2.z * ss.z) * scale);
        o1.w = to_tf32((x1.w * cc.w - x2.w * ss.w) * scale);
        o2.x = to_tf32((x2.x * cc.x + x1.x * ss.x) * scale);
        o2.y = to_tf32((x2.y * cc.y + x1.y * ss.y) * scale);
        o2.z = to_tf32((x2.z * cc.z + x1.z * ss.z) * scale);
        o2.w = to_tf32((x2.w * cc.w + x1.w * ss.w) * scale);
        *(float4*)(&sQ[r * QK_STRIDE + c4]) = o1;
        *(float4*)(&sQ[r * QK_STRIDE + c4 + 36]) = o2;
    }
    if (tid < QT) {
        int t = q0 + tid;
        int s = 0;
#pragma unroll
        for (int j = 1; j < NCU; j++)
            if (sCu[j] <= t) s = j;
        sSegQ[tid] = s;
    }
    __syncthreads();

    const int seg_lo = sSegQ[0];
    const int seg_hi = sSegQ[QT - 1];
    const int k_end = sCu[seg_hi + 1];
    const int kc0 = (sCu[seg_lo] / KT) * KT;

    const int r0 = wid * 16 + gid;
    const int segq0 = sSegQ[r0];
    const int segq1 = sSegQ[r0 + 8];

    float m0 = -1e30f, m1 = -1e30f, l0 = 0.f, l1 = 0.f;
    float O[9][4];
#pragma unroll
    for (int no = 0; no < 9; no++)
#pragma unroll
        for (int r = 0; r < 4; r++) O[no][r] = 0.f;

    const uint32_t* uQ = (const uint32_t*)sQ;
    const uint32_t* uK = (const uint32_t*)sK;
    const uint32_t* uV = (const uint32_t*)sV;
    const uint32_t* uP = (const uint32_t*)sP;

    for (int kc = kc0; kc < k_end; kc += KT) {
        // ---- load K: partial sum + bias + RoPE ----
        for (int i = tid; i < KT * 9; i += 256) {
            int r = i / 9, c4 = (i % 9) * 4;
            int t = kc + r;
            size_t base = (size_t)t * D_DIM + h * DH;
            float4 a1 = *(const float4*)(pk0 + base + c4);
            float4 b1 = *(const float4*)(pk1 + base + c4);
            float4 a2 = *(const float4*)(pk0 + base + c4 + 36);
            float4 b2 = *(const float4*)(pk1 + base + c4 + 36);
            float4 g1 = *(const float4*)(bk + h * DH + c4);
            float4 g2 = *(const float4*)(bk + h * DH + c4 + 36);
            float4 x1, x2;
            x1.x = a1.x + b1.x + g1.x; x1.y = a1.y + b1.y + g1.y;
            x1.z = a1.z + b1.z + g1.z; x1.w = a1.w + b1.w + g1.w;
            x2.x = a2.x + b2.x + g2.x; x2.y = a2.y + b2.y + g2.y;
            x2.z = a2.z + b2.z + g2.z; x2.w = a2.w + b2.w + g2.w;
            float4 cc = *(const float4*)(cosp + (size_t)t * DH + c4);
            float4 ss = *(const float4*)(sinp + (size_t)t * DH + c4);
            float4 o1, o2;
            o1.x = to_tf32(x1.x * cc.x - x2.x * ss.x);
            o1.y = to_tf32(x1.y * cc.y - x2.y * ss.y);
            o1.z = to_tf32(x1.z * cc.z - x2.z * ss.z);
            o1.w = to_tf32(x1.w * cc.w - x2.w * ss.w);
            o2.x = to_tf32(x2.x * cc.x + x1.x * ss.x);
            o2.y = to_tf32(x2.y * cc.y + x1.y * ss.y);
            o2.z = to_tf32(x2.z * cc.z + x1.z * ss.z);
            o2.w = to_tf32(x2.w * cc.w + x1.w * ss.w);
            *(float4*)(&sK[r * QK_STRIDE + c4]) = o1;
            *(float4*)(&sK[r * QK_STRIDE + c4 + 36]) = o2;
        }
        // ---- load V: partial sum + bias ----
        for (int i = tid; i < KT * (DH / 4); i += 256) {
            int r = i / (DH / 4), c4 = (i % (DH / 4)) * 4;
            size_t base = (size_t)(kc + r) * D_DIM + h * DH + c4;
            float4 a = *(const float4*)(pv0 + base);
            float4 b = *(const float4*)(pv1 + base);
            float4 g = *(const float4*)(bv + h * DH + c4);
            float4 vv;
            vv.x = to_tf32(a.x + b.x + g.x);
            vv.y = to_tf32(a.y + b.y + g.y);
            vv.z = to_tf32(a.z + b.z + g.z);
            vv.w = to_tf32(a.w + b.w + g.w);
            *(float4*)(&sV[r * V_STRIDE + c4]) = vv;
        }
        if (tid < KT) {
            int t = kc + tid;
            int s = 0;
#pragma unroll
            for (int j = 1; j < NCU; j++)
                if (sCu[j] <= t) s = j;
            sSegK[tid] = s;
        }
        __syncthreads();

        // ---- S = Q K^T ----
        float accS[8][4];
#pragma unroll
        for (int na = 0; na < 8; na++)
#pragma unroll
            for (int r = 0; r < 4; r++) accS[na][r] = 0.f;

#pragma unroll
        for (int ks = 0; ks < 9; ks++) {
            const int k0 = ks * 8;
            uint32_t a0 = uQ[r0 * QK_STRIDE + k0 + tig];
            uint32_t a1 = uQ[(r0 + 8) * QK_STRIDE + k0 + tig];
            uint32_t a2 = uQ[r0 * QK_STRIDE + k0 + tig + 4];
            uint32_t a3 = uQ[(r0 + 8) * QK_STRIDE + k0 + tig + 4];
#pragma unroll
            for (int na = 0; na < 8; na++) {
                uint32_t b0 = uK[(na * 8 + gid) * QK_STRIDE + k0 + tig];
                uint32_t b1 = uK[(na * 8 + gid) * QK_STRIDE + k0 + tig + 4];
                mma_tf32(accS[na][0], accS[na][1], accS[na][2], accS[na][3],
                         a0, a1, a2, a3, b0, b1);
            }
        }

        // ---- mask ----
#pragma unroll
        for (int na = 0; na < 8; na++) {
            int c0 = na * 8 + tig * 2;
            int sk0 = sSegK[c0], sk1 = sSegK[c0 + 1];
            if (sk0 != segq0) accS[na][0] = -1e30f;
            if (sk1 != segq0) accS[na][1] = -1e30f;
            if (sk0 != segq1) accS[na][2] = -1e30f;
            if (sk1 != segq1) accS[na][3] = -1e30f;
        }

        // ---- online softmax ----
        float mt0 = -1e30f, mt1 = -1e30f;
#pragma unroll
        for (int na = 0; na < 8; na++) {
            mt0 = fmaxf(mt0, fmaxf(accS[na][0], accS[na][1]));
            mt1 = fmaxf(mt1, fmaxf(accS[na][2], accS[na][3]));
        }
        mt0 = fmaxf(mt0, __shfl_xor_sync(0xffffffffu, mt0, 1));
        mt0 = fmaxf(mt0, __shfl_xor_sync(0xffffffffu, mt0, 2));
        mt1 = fmaxf(mt1, __shfl_xor_sync(0xffffffffu, mt1, 1));
        mt1 = fmaxf(mt1, __shfl_xor_sync(0xffffffffu, mt1, 2));
        float mn0 = fmaxf(m0, mt0);
        float mn1 = fmaxf(m1, mt1);

        float ls0 = 0.f, ls1 = 0.f;
#pragma unroll
        for (int na = 0; na < 8; na++) {
            float p00 = (accS[na][0] < -1e29f) ? 0.f : to_tf32(__expf(accS[na][0] - mn0));
            float p01 = (accS[na][1] < -1e29f) ? 0.f : to_tf32(__expf(accS[na][1] - mn0));
            float p10 = (accS[na][2] < -1e29f) ? 0.f : to_tf32(__expf(accS[na][2] - mn1));
            float p11 = (accS[na][3] < -1e29f) ? 0.f : to_tf32(__expf(accS[na][3] - mn1));
            ls0 += p00 + p01;
            ls1 += p10 + p11;
            int c0 = na * 8 + tig * 2;
            *(float2*)(&sP[r0 * P_STRIDE + c0]) = make_float2(p00, p01);
            *(float2*)(&sP[(r0 + 8) * P_STRIDE + c0]) = make_float2(p10, p11);
        }
        ls0 += __shfl_xor_sync(0xffffffffu, ls0, 1);
        ls0 += __shfl_xor_sync(0xffffffffu, ls0, 2);
        ls1 += __shfl_xor_sync(0xffffffffu, ls1, 1);
        ls1 += __shfl_xor_sync(0xffffffffu, ls1, 2);

        float al0 = __expf(m0 - mn0);
        float al1 = __expf(m1 - mn1);
        l0 = l0 * al0 + ls0;
        l1 = l1 * al1 + ls1;
        m0 = mn0; m1 = mn1;

#pragma unroll
        for (int no = 0; no < 9; no++) {
            O[no][0] *= al0; O[no][1] *= al0;
            O[no][2] *= al1; O[no][3] *= al1;
        }
        __syncwarp();

        // ---- O += P V ----
#pragma unroll
        for (int ks = 0; ks < 8; ks++) {
            const int k0 = ks * 8;
            uint32_t a0 = uP[r0 * P_STRIDE + k0 + tig];
            uint32_t a1 = uP[(r0 + 8) * P_STRIDE + k0 + tig];
            uint32_t a2 = uP[r0 * P_STRIDE + k0 + tig + 4];
            uint32_t a3 = uP[(r0 + 8) * P_STRIDE + k0 + tig + 4];
#pragma unroll
            for (int no = 0; no < 9; no++) {
                uint32_t b0 = uV[(k0 + tig) * V_STRIDE + no * 8 + gid];
                uint32_t b1 = uV[(k0 + tig + 4) * V_STRIDE + no * 8 + gid];
                mma_tf32(O[no][0], O[no][1], O[no][2], O[no][3],
                         a0, a1, a2, a3, b0, b1);
            }
        }
        __syncthreads();
    }

    float il0 = 1.f / l0;
    float il1 = 1.f / l1;
    size_t ob0 = (size_t)(q0 + r0) * D_DIM + h * DH;
    size_t ob1 = (size_t)(q0 + r0 + 8) * D_DIM + h * DH;
#pragma unroll
    for (int no = 0; no < 9; no++) {
        int c0 = no * 8 + tig * 2;
        *(float2*)(out + ob0 + c0) = make_float2(to_tf32(O[no][0] * il0), to_tf32(O[no][1] * il0));
        *(float2*)(out + ob1 + c0) = make_float2(to_tf32(O[no][2] * il1), to_tf32(O[no][3] * il1));
    }
}

// ---------------- host launch ----------------
extern "C" void kernel_launch(void* const* d_in, const int* in_sizes, int n_in,
                              void* d_out, int out_size)
{
    const float* hs   = (const float*)d_in[0];
    const int*   cu   = (const int*)  d_in[1];
    const float* cosp = (const float*)d_in[2];
    const float* sinp = (const float*)d_in[3];
    const float* Wq   = (const float*)d_in[4];
    const float* bq   = (const float*)d_in[5];
    const float* Wk   = (const float*)d_in[6];
    const float* bk   = (const float*)d_in[7];
    const float* Wv   = (const float*)d_in[8];
    const float* bv   = (const float*)d_in[9];
    const float* Wo   = (const float*)d_in[10];
    const float* bo   = (const float*)d_in[11];
    float* out = (float*)d_out;

    float *part, *attn, *hsr, *wr;
    cudaGetSymbolAddress((void**)&part, g_part);
    cudaGetSymbolAddress((void**)&attn, g_attn);
    cudaGetSymbolAddress((void**)&hsr, g_hsr);
    cudaGetSymbolAddress((void**)&wr, g_wr);
    float* wqr = wr;
    float* wkr = wr + (size_t)D_DIM * D_DIM;
    float* wvr = wr + 2 * (size_t)D_DIM * D_DIM;
    float* wor = wr + 3 * (size_t)D_DIM * D_DIM;

    // pre-round hs + weights (grid x sized for the LARGEST segment: hs)
    int n4hs = TD / 4;
    dim3 rgrid((n4hs + 255) / 256, 5);
    round_tf32_kernel<<<rgrid, 256>>>(hs, Wq, Wk, Wv, Wo);

    cudaFuncSetAttribute(gemm_cp_tf32,
                         cudaFuncAttributeMaxDynamicSharedMemorySize, GEMM_SMEM);

    // fused QKV, split-K x2: z = proj*2 + half -> g_part slots 0..5
    dim3 qkv_grid(D_DIM / BN, T_TOK / BM, 6);   // (9, 8, 6)
    gemm_cp_tf32<<<qkv_grid, 256, GEMM_SMEM>>>(hsr, wqr, wkr, wvr, part);

    // attention: fused RoPE + QKV partial-sum + bias
    cudaFuncSetAttribute(attn_kernel,
                         cudaFuncAttributeMaxDynamicSharedMemorySize, ATTN_SMEM);
    attn_kernel<<<dim3(T_TOK / QT, H_NUM), 256, ATTN_SMEM>>>(
        part + 0 * (size_t)TD, part + 1 * (size_t)TD,
        part + 2 * (size_t)TD, part + 3 * (size_t)TD,
        part + 4 * (size_t)TD, part + 5 * (size_t)TD,
        bq, bk, bv, cu, cosp, sinp, attn);

    // O projection, split-K x2 -> slots 6,7 (Cbase offset by 6*TD; z in {0,1})
    dim3 o_grid(D_DIM / BN, T_TOK / BM, 2);     // (9, 8, 2)
    gemm_cp_tf32<<<o_grid, 256, GEMM_SMEM>>>(attn, wor, wor, wor, part + 6 * (size_t)TD);

    // final reduction: out = p6 + p7 + bo
    reduce_out_kernel<<<(TD / 4 + 255) / 256, 256>>>(
        part + 6 * (size_t)TD, part + 7 * (size_t)TD, bo, out);
}

// round 15
// speedup vs baseline: 1.3447x; 1.1728x over previous
#include <cuda_runtime.h>
#include <cuda_bf16.h>
#include <cstdint>
#include <math.h>

#define T_TOK 2048
#define D_DIM 1152
#define H_NUM 16
#define DH 72
#define NCU 9
#define TD (T_TOK * D_DIM)

// ---------------- scratch (no allocations allowed) ----------------
// g_part slots: 0,1=q halves; 2,3=k; 4,5=v; 6,7=o-proj partials
__device__ float g_part[8][TD];
__device__ float g_attn[TD];
__device__ float g_hsr[TD];
__device__ float g_wr[4][D_DIM * D_DIM];
__device__ float g_qf[TD];   // finalized q (sum+bias+rope+scale, tf32)
__device__ float g_kf[TD];   // finalized k
__device__ float g_vf[TD];   // finalized v

__device__ __forceinline__ float to_tf32(float x) {
    float y; asm("cvt.rna.tf32.f32 %0, %1;" : "=f"(y) : "f"(x)); return y;
}

__device__ __forceinline__ uint32_t smem_u32(const void* p) {
    uint32_t a;
    asm("{ .reg .u64 t; cvta.to.shared.u64 t, %1; cvt.u32.u64 %0, t; }" : "=r"(a) : "l"(p));
    return a;
}
__device__ __forceinline__ void cp16(uint32_t s, const void* g) {
    asm volatile("cp.async.ca.shared.global [%0], [%1], 16;" :: "r"(s), "l"(g));
}
#define CP_COMMIT() asm volatile("cp.async.commit_group;" ::: "memory")
#define CP_WAIT(n)  asm volatile("cp.async.wait_group %0;" :: "n"(n) : "memory")

__device__ __forceinline__ void mma_tf32(float& d0, float& d1, float& d2, float& d3,
                                         uint32_t a0, uint32_t a1, uint32_t a2, uint32_t a3,
                                         uint32_t b0, uint32_t b1) {
    asm volatile(
        "mma.sync.aligned.m16n8k8.row.col.f32.tf32.tf32.f32 "
        "{%0,%1,%2,%3}, {%4,%5,%6,%7}, {%8,%9}, {%0,%1,%2,%3};"
        : "+f"(d0), "+f"(d1), "+f"(d2), "+f"(d3)
        : "r"(a0), "r"(a1), "r"(a2), "r"(a3), "r"(b0), "r"(b1));
}

// ---------------- pre-round pass: tf32-round hs + 4 weights ----------------
__global__ void round_tf32_kernel(const float* __restrict__ hs,
                                  const float* __restrict__ wq, const float* __restrict__ wk,
                                  const float* __restrict__ wv, const float* __restrict__ wo)
{
    const int seg = blockIdx.y;
    const float* src;
    float* dst;
    int n4;
    if (seg == 0) { src = hs; dst = g_hsr;   n4 = TD / 4; }
    else {
        const float* ws[4] = {wq, wk, wv, wo};
        src = ws[seg - 1]; dst = g_wr[seg - 1]; n4 = D_DIM * D_DIM / 4;
    }
    int idx = blockIdx.x * blockDim.x + threadIdx.x;
    if (idx >= n4) return;
    float4 v = ((const float4*)src)[idx];
    v.x = to_tf32(v.x); v.y = to_tf32(v.y); v.z = to_tf32(v.z); v.w = to_tf32(v.w);
    ((float4*)dst)[idx] = v;
}

// ============ cp.async 3-stage split-K tf32 GEMM: Cpart = A @ W^T (half K) ============
// CTA tile 256x128, 8 warps 4x2, warp tile 64x64. KCH=32 (4 ksteps per chunk).
#define BM 256
#define BN 128
#define KCH 32
#define KHALF 576
#define NCHUNK_H (KHALF / KCH)   // 18
#define SPAD 36
#define STAGES 3
#define A_STG (BM * SPAD)        // 9216 floats
#define B_STG (BN * SPAD)        // 4608 floats
#define GEMM_SMEM (STAGES * (A_STG + B_STG) * 4)   // 165888 bytes

__global__ __launch_bounds__(256) void gemm_cp_tf32(
    const float* __restrict__ A,
    const float* __restrict__ W0, const float* __restrict__ W1, const float* __restrict__ W2,
    float* __restrict__ Cbase)
{
    extern __shared__ float smemf[];
    float* sA = smemf;
    float* sB = smemf + STAGES * A_STG;
    const uint32_t uAaddr = smem_u32(sA);
    const uint32_t uBaddr = smem_u32(sB);

    const int z = blockIdx.z;
    const int proj = z >> 1;
    const int koff = (z & 1) * KHALF;
    const float* Bw = (proj == 0) ? W0 : (proj == 1) ? W1 : W2;
    float* C = Cbase + (size_t)z * TD;

    const int tid = threadIdx.x;
    const int wid = tid >> 5;
    const int lane = tid & 31;
    const int gid = lane >> 2;
    const int tig = lane & 3;
    const int wm = wid & 3;
    const int wn = wid >> 2;

    const int bm = blockIdx.y * BM;
    const int bn = blockIdx.x * BN;

    auto issue = [&](int c, int stg) {
        // A: 2048 float4 (256 rows x 8), 8 per thread
#pragma unroll
        for (int i = 0; i < 8; i++) {
            int idx = i * 256 + tid;
            int row = idx >> 3;
            int c4 = (idx & 7) * 4;
            uint32_t off = (uint32_t)(stg * A_STG + row * SPAD + c4) * 4u;
            cp16(uAaddr + off, A + (size_t)(bm + row) * D_DIM + koff + c * KCH + c4);
        }
        // B: 1024 float4 (128 rows x 8), 4 per thread
#pragma unroll
        for (int i = 0; i < 4; i++) {
            int idx = i * 256 + tid;
            int row = idx >> 3;
            int c4 = (idx & 7) * 4;
            uint32_t off = (uint32_t)(stg * B_STG + row * SPAD + c4) * 4u;
            cp16(uBaddr + off, Bw + (size_t)(bn + row) * D_DIM + koff + c * KCH + c4);
        }
    };

    float acc[4][8][4];
#pragma unroll
    for (int i = 0; i < 4; i++)
#pragma unroll
        for (int j = 0; j < 8; j++)
#pragma unroll
            for (int r = 0; r < 4; r++) acc[i][j][r] = 0.f;

    issue(0, 0); CP_COMMIT();
    issue(1, 1); CP_COMMIT();

    int stg = 0;
    int wstg = STAGES - 1;
    for (int c = 0; c < NCHUNK_H; c++) {
        CP_WAIT(1);
        __syncthreads();

        const uint32_t* uA = (const uint32_t*)(sA + stg * A_STG);
        const uint32_t* uB = (const uint32_t*)(sB + stg * B_STG);

#pragma unroll
        for (int ks = 0; ks < 4; ks++) {
            const int k0 = ks * 8;
            uint32_t af[4][4], bf[8][2];
#pragma unroll
            for (int ma = 0; ma < 4; ma++) {
                int r0 = (wm * 64 + ma * 16 + gid) * SPAD;
                af[ma][0] = uA[r0 + k0 + tig];
                af[ma][1] = uA[r0 + 8 * SPAD + k0 + tig];
                af[ma][2] = uA[r0 + k0 + tig + 4];
                af[ma][3] = uA[r0 + 8 * SPAD + k0 + tig + 4];
            }
#pragma unroll
            for (int na = 0; na < 8; na++) {
                int r0 = (wn * 64 + na * 8 + gid) * SPAD;
                bf[na][0] = uB[r0 + k0 + tig];
                bf[na][1] = uB[r0 + k0 + tig + 4];
            }
#pragma unroll
            for (int ma = 0; ma < 4; ma++)
#pragma unroll
                for (int na = 0; na < 8; na++)
                    mma_tf32(acc[ma][na][0], acc[ma][na][1], acc[ma][na][2], acc[ma][na][3],
                             af[ma][0], af[ma][1], af[ma][2], af[ma][3],
                             bf[na][0], bf[na][1]);
        }

        if (c + 2 < NCHUNK_H) issue(c + 2, wstg);
        CP_COMMIT();
        if (++stg == STAGES) stg = 0;
        if (++wstg == STAGES) wstg = 0;
    }

#pragma unroll
    for (int ma = 0; ma < 4; ma++) {
        int row = bm + wm * 64 + ma * 16 + gid;
#pragma unroll
        for (int na = 0; na < 8; na++) {
            int col = bn + wn * 64 + na * 8 + tig * 2;
            *(float2*)(C + (size_t)row * D_DIM + col) = make_float2(acc[ma][na][0], acc[ma][na][1]);
            *(float2*)(C + (size_t)(row + 8) * D_DIM + col) = make_float2(acc[ma][na][2], acc[ma][na][3]);
        }
    }
}

// ---------------- finalize QKV: sum partials + bias (+rope/scale for q,k), tf32 ----------------
__global__ void finalize_qkv(const float* pq0, const float* pq1,
                             const float* pk0, const float* pk1,
                             const float* pv0, const float* pv1,
                             const float* bq, const float* bk, const float* bv,
                             const float* cosp, const float* sinp)
{
    const float scale = rsqrtf((float)DH);
    int idx = blockIdx.x * blockDim.x + threadIdx.x;
    if (blockIdx.y == 0) {
        // q,k with rope: one thread per (t, h, c4-pair)
        if (idx >= T_TOK * H_NUM * 9) return;
        int c4 = (idx % 9) * 4;
        int th = idx / 9;
        int h = th % H_NUM;
        int t = th / H_NUM;
        size_t base = (size_t)t * D_DIM + h * DH;
        float4 cc = *(const float4*)(cosp + (size_t)t * DH + c4);
        float4 ss = *(const float4*)(sinp + (size_t)t * DH + c4);

        // q
        {
            float4 a1 = *(const float4*)(pq0 + base + c4);
            float4 b1 = *(const float4*)(pq1 + base + c4);
            float4 a2 = *(const float4*)(pq0 + base + c4 + 36);
            float4 b2 = *(const float4*)(pq1 + base + c4 + 36);
            float4 g1 = *(const float4*)(bq + h * DH + c4);
            float4 g2 = *(const float4*)(bq + h * DH + c4 + 36);
            float4 x1, x2;
            x1.x = a1.x + b1.x + g1.x; x1.y = a1.y + b1.y + g1.y;
            x1.z = a1.z + b1.z + g1.z; x1.w = a1.w + b1.w + g1.w;
            x2.x = a2.x + b2.x + g2.x; x2.y = a2.y + b2.y + g2.y;
            x2.z = a2.z + b2.z + g2.z; x2.w = a2.w + b2.w + g2.w;
            float4 o1, o2;
            o1.x = to_tf32((x1.x * cc.x - x2.x * ss.x) * scale);
            o1.y = to_tf32((x1.y * cc.y - x2.y * ss.y) * scale);
            o1.z = to_tf32((x1.z * cc.z - x2.z * ss.z) * scale);
            o1.w = to_tf32((x1.w * cc.w - x2.w * ss.w) * scale);
            o2.x = to_tf32((x2.x * cc.x + x1.x * ss.x) * scale);
            o2.y = to_tf32((x2.y * cc.y + x1.y * ss.y) * scale);
            o2.z = to_tf32((x2.z * cc.z + x1.z * ss.z) * scale);
            o2.w = to_tf32((x2.w * cc.w + x1.w * ss.w) * scale);
            *(float4*)(g_qf + base + c4) = o1;
            *(float4*)(g_qf + base + c4 + 36) = o2;
        }
        // k (no scale)
        {
            float4 a1 = *(const float4*)(pk0 + base + c4);
            float4 b1 = *(const float4*)(pk1 + base + c4);
            float4 a2 = *(const float4*)(pk0 + base + c4 + 36);
            float4 b2 = *(const float4*)(pk1 + base + c4 + 36);
            float4 g1 = *(const float4*)(bk + h * DH + c4);
            float4 g2 = *(const float4*)(bk + h * DH + c4 + 36);
            float4 x1, x2;
            x1.x = a1.x + b1.x + g1.x; x1.y = a1.y + b1.y + g1.y;
            x1.z = a1.z + b1.z + g1.z; x1.w = a1.w + b1.w + g1.w;
            x2.x = a2.x + b2.x + g2.x; x2.y = a2.y + b2.y + g2.y;
            x2.z = a2.z + b2.z + g2.z; x2.w = a2.w + b2.w + g2.w;
            float4 o1, o2;
            o1.x = to_tf32(x1.x * cc.x - x2.x * ss.x);
            o1.y = to_tf32(x1.y * cc.y - x2.y * ss.y);
            o1.z = to_tf32(x1.z * cc.z - x2.z * ss.z);
            o1.w = to_tf32(x1.w * cc.w - x2.w * ss.w);
            o2.x = to_tf32(x2.x * cc.x + x1.x * ss.x);
            o2.y = to_tf32(x2.y * cc.y + x1.y * ss.y);
            o2.z = to_tf32(x2.z * cc.z + x1.z * ss.z);
            o2.w = to_tf32(x2.w * cc.w + x1.w * ss.w);
            *(float4*)(g_kf + base + c4) = o1;
            *(float4*)(g_kf + base + c4 + 36) = o2;
        }
    } else {
        // v: plain sum + bias
        if (idx >= TD / 4) return;
        int col = (idx * 4) % D_DIM;
        float4 a = ((const float4*)pv0)[idx];
        float4 b = ((const float4*)pv1)[idx];
        float4 g = *(const float4*)(bv + col);
        float4 o;
        o.x = to_tf32(a.x + b.x + g.x);
        o.y = to_tf32(a.y + b.y + g.y);
        o.z = to_tf32(a.z + b.z + g.z);
        o.w = to_tf32(a.w + b.w + g.w);
        ((float4*)g_vf)[idx] = o;
    }
}

// ---------------- O-projection reduction: out = p6 + p7 + bo ----------------
__global__ void reduce_out_kernel(const float* __restrict__ p0, const float* __restrict__ p1,
                                  const float* __restrict__ bo, float* __restrict__ out)
{
    int idx = blockIdx.x * blockDim.x + threadIdx.x;
    if (idx >= TD / 4) return;
    int col = (idx * 4) % D_DIM;
    float4 a = ((const float4*)p0)[idx];
    float4 b = ((const float4*)p1)[idx];
    float4 bb = *(const float4*)(bo + col);
    float4 o;
    o.x = a.x + b.x + bb.x;
    o.y = a.y + b.y + bb.y;
    o.z = a.z + b.z + bb.z;
    o.w = a.w + b.w + bb.w;
    ((float4*)out)[idx] = o;
}

// ---------------- Segment-masked flash attention (tf32 mma.sync, cp.async K/V pipeline) ----------------
// grid (T/128, H), 256 threads (8 warps x 16 query rows). K-tile 64, 2-stage double buffer.
#define QT 128
#define KT 64
#define QK_STRIDE 76
#define V_STRIDE 72
#define P_STRIDE 68
#define SQ_FLOATS (QT * QK_STRIDE)            // 9728
#define SK_FLOATS (KT * QK_STRIDE)            // 4864
#define SV_FLOATS (KT * V_STRIDE)             // 4608
#define SP_FLOATS (QT * P_STRIDE)             // 8704
#define ATTN_SMEM ((SQ_FLOATS + 2 * SK_FLOATS + 2 * SV_FLOATS + SP_FLOATS) * 4)  // 149504

__global__ __launch_bounds__(256) void attn_kernel(
    const float* __restrict__ qf, const float* __restrict__ kf,
    const float* __restrict__ vf, const int* __restrict__ cu,
    float* __restrict__ out)
{
    extern __shared__ float smemf[];
    float* sQ = smemf;                             // 128 x 76
    float* sKb = sQ + SQ_FLOATS;                   // 2 x (64 x 76)
    float* sVb = sKb + 2 * SK_FLOATS;              // 2 x (64 x 72)
    float* sP = sVb + 2 * SV_FLOATS;               // 128 x 68
    __shared__ int sCu[NCU];
    __shared__ int sSegQ[QT];
    __shared__ int sSegK[2][KT];

    const uint32_t uKaddr = smem_u32(sKb);
    const uint32_t uVaddr = smem_u32(sVb);

    const int tid = threadIdx.x;
    const int wid = tid >> 5;
    const int lane = tid & 31;
    const int gid = lane >> 2;
    const int tig = lane & 3;
    const int h = blockIdx.y;
    const int q0 = blockIdx.x * QT;

    if (tid < NCU) sCu[tid] = cu[tid];
    __syncthreads();

    // ---- load Q (pre-finalized): 128 rows x 18 float4 ----
    for (int i = tid; i < QT * 18; i += 256) {
        int r = i / 18, c4 = (i % 18) * 4;
        *(float4*)(&sQ[r * QK_STRIDE + c4]) =
            *(const float4*)(qf + (size_t)(q0 + r) * D_DIM + h * DH + c4);
    }
    if (tid < QT) {
        int t = q0 + tid;
        int s = 0;
#pragma unroll
        for (int j = 1; j < NCU; j++)
            if (sCu[j] <= t) s = j;
        sSegQ[tid] = s;
    }
    __syncthreads();

    const int seg_lo = sSegQ[0];
    const int seg_hi = sSegQ[QT - 1];
    const int k_end = sCu[seg_hi + 1];
    const int kc0 = (sCu[seg_lo] / KT) * KT;

    const int r0 = wid * 16 + gid;
    const int segq0 = sSegQ[r0];
    const int segq1 = sSegQ[r0 + 8];

    // cp.async loader for one K/V tile into stage b: 2304 float4, 9 per thread
    auto issue_kv = [&](int kc, int b) {
#pragma unroll
        for (int i = 0; i < 9; i++) {
            int idx = i * 256 + tid;
            if (idx < KT * 18) {
                int row = idx / 18, c4 = (idx % 18) * 4;
                cp16(uKaddr + (uint32_t)(b * SK_FLOATS + row * QK_STRIDE + c4) * 4u,
                     kf + (size_t)(kc + row) * D_DIM + h * DH + c4);
            } else {
                int j = idx - KT * 18;
                int row = j / 18, c4 = (j % 18) * 4;
                cp16(uVaddr + (uint32_t)(b * SV_FLOATS + row * V_STRIDE + c4) * 4u,
                     vf + (size_t)(kc + row) * D_DIM + h * DH + c4);
            }
        }
    };

    float m0 = -1e30f, m1 = -1e30f, l0 = 0.f, l1 = 0.f;
    float O[9][4];
#pragma unroll
    for (int no = 0; no < 9; no++)
#pragma unroll
        for (int r = 0; r < 4; r++) O[no][r] = 0.f;

    const uint32_t* uQ = (const uint32_t*)sQ;
    const uint32_t* uP = (const uint32_t*)sP;

    // prologue: first tile
    issue_kv(kc0, 0); CP_COMMIT();
    if (tid < KT) {
        int t = kc0 + tid;
        int s = 0;
#pragma unroll
        for (int j = 1; j < NCU; j++)
            if (sCu[j] <= t) s = j;
        sSegK[0][tid] = s;
    }

    int buf = 0;
    for (int kc = kc0; kc < k_end; kc += KT) {
        CP_WAIT(0);
        __syncthreads();

        // issue next tile into other buffer; overlap with this tile's compute
        if (kc + KT < k_end) {
            issue_kv(kc + KT, buf ^ 1); CP_COMMIT();
            if (tid < KT) {
                int t = kc + KT + tid;
                int s = 0;
#pragma unroll
                for (int j = 1; j < NCU; j++)
                    if (sCu[j] <= t) s = j;
                sSegK[buf ^ 1][tid] = s;
            }
        }

        const uint32_t* uK = (const uint32_t*)(sKb + buf * SK_FLOATS);
        const uint32_t* uV = (const uint32_t*)(sVb + buf * SV_FLOATS);
        const int* segK = sSegK[buf];

        // ---- S = Q K^T ----
        float accS[8][4];
#pragma unroll
        for (int na = 0; na < 8; na++)
#pragma unroll
            for (int r = 0; r < 4; r++) accS[na][r] = 0.f;

#pragma unroll
        for (int ks = 0; ks < 9; ks++) {
            const int k0 = ks * 8;
            uint32_t a0 = uQ[r0 * QK_STRIDE + k0 + tig];
            uint32_t a1 = uQ[(r0 + 8) * QK_STRIDE + k0 + tig];
            uint32_t a2 = uQ[r0 * QK_STRIDE + k0 + tig + 4];
            uint32_t a3 = uQ[(r0 + 8) * QK_STRIDE + k0 + tig + 4];
#pragma unroll
            for (int na = 0; na < 8; na++) {
                uint32_t b0 = uK[(na * 8 + gid) * QK_STRIDE + k0 + tig];
                uint32_t b1 = uK[(na * 8 + gid) * QK_STRIDE + k0 + tig + 4];
                mma_tf32(accS[na][0], accS[na][1], accS[na][2], accS[na][3],
                         a0, a1, a2, a3, b0, b1);
            }
        }

        // ---- mask ----
#pragma unroll
        for (int na = 0; na < 8; na++) {
            int c0 = na * 8 + tig * 2;
            int sk0 = segK[c0], sk1 = segK[c0 + 1];
            if (sk0 != segq0) accS[na][0] = -1e30f;
            if (sk1 != segq0) accS[na][1] = -1e30f;
            if (sk0 != segq1) accS[na][2] = -1e30f;
            if (sk1 != segq1) accS[na][3] = -1e30f;
        }

        // ---- online softmax ----
        float mt0 = -1e30f, mt1 = -1e30f;
#pragma unroll
        for (int na = 0; na < 8; na++) {
            mt0 = fmaxf(mt0, fmaxf(accS[na][0], accS[na][1]));
            mt1 = fmaxf(mt1, fmaxf(accS[na][2], accS[na][3]));
        }
        mt0 = fmaxf(mt0, __shfl_xor_sync(0xffffffffu, mt0, 1));
        mt0 = fmaxf(mt0, __shfl_xor_sync(0xffffffffu, mt0, 2));
        mt1 = fmaxf(mt1, __shfl_xor_sync(0xffffffffu, mt1, 1));
        mt1 = fmaxf(mt1, __shfl_xor_sync(0xffffffffu, mt1, 2));
        float mn0 = fmaxf(m0, mt0);
        float mn1 = fmaxf(m1, mt1);

        float ls0 = 0.f, ls1 = 0.f;
#pragma unroll
        for (int na = 0; na < 8; na++) {
            float p00 = (accS[na][0] < -1e29f) ? 0.f : to_tf32(__expf(accS[na][0] - mn0));
            float p01 = (accS[na][1] < -1e29f) ? 0.f : to_tf32(__expf(accS[na][1] - mn0));
            float p10 = (accS[na][2] < -1e29f) ? 0.f : to_tf32(__expf(accS[na][2] - mn1));
            float p11 = (accS[na][3] < -1e29f) ? 0.f : to_tf32(__expf(accS[na][3] - mn1));
            ls0 += p00 + p01;
            ls1 += p10 + p11;
            int c0 = na * 8 + tig * 2;
            *(float2*)(&sP[r0 * P_STRIDE + c0]) = make_float2(p00, p01);
            *(float2*)(&sP[(r0 + 8) * P_STRIDE + c0]) = make_float2(p10, p11);
        }
        ls0 += __shfl_xor_sync(0xffffffffu, ls0, 1);
        ls0 += __shfl_xor_sync(0xffffffffu, ls0, 2);
        ls1 += __shfl_xor_sync(0xffffffffu, ls1, 1);
        ls1 += __shfl_xor_sync(0xffffffffu, ls1, 2);

        float al0 = __expf(m0 - mn0);
        float al1 = __expf(m1 - mn1);
        l0 = l0 * al0 + ls0;
        l1 = l1 * al1 + ls1;
        m0 = mn0; m1 = mn1;

#pragma unroll
        for (int no = 0; no < 9; no++) {
            O[no][0] *= al0; O[no][1] *= al0;
            O[no][2] *= al1; O[no][3] *= al1;
        }
        __syncwarp();

        // ---- O += P V ----
#pragma unroll
        for (int ks = 0; ks < 8; ks++) {
            const int k0 = ks * 8;
            uint32_t a0 = uP[r0 * P_STRIDE + k0 + tig];
            uint32_t a1 = uP[(r0 + 8) * P_STRIDE + k0 + tig];
            uint32_t a2 = uP[r0 * P_STRIDE + k0 + tig + 4];
            uint32_t a3 = uP[(r0 + 8) * P_STRIDE + k0 + tig + 4];
#pragma unroll
            for (int no = 0; no < 9; no++) {
                uint32_t b0 = uV[(k0 + tig) * V_STRIDE + no * 8 + gid];
                uint32_t b1 = uV[(k0 + tig + 4) * V_STRIDE + no * 8 + gid];
                mma_tf32(O[no][0], O[no][1], O[no][2], O[no][3],
                         a0, a1, a2, a3, b0, b1);
            }
        }
        buf ^= 1;
    }

    float il0 = 1.f / l0;
    float il1 = 1.f / l1;
    size_t ob0 = (size_t)(q0 + r0) * D_DIM + h * DH;
    size_t ob1 = (size_t)(q0 + r0 + 8) * D_DIM + h * DH;
#pragma unroll
    for (int no = 0; no < 9; no++) {
        int c0 = no * 8 + tig * 2;
        *(float2*)(out + ob0 + c0) = make_float2(to_tf32(O[no][0] * il0), to_tf32(O[no][1] * il0));
        *(float2*)(out + ob1 + c0) = make_float2(to_tf32(O[no][2] * il1), to_tf32(O[no][3] * il1));
    }
}

// ---------------- host launch ----------------
extern "C" void kernel_launch(void* const* d_in, const int* in_sizes, int n_in,
                              void* d_out, int out_size)
{
    const float* hs   = (const float*)d_in[0];
    const int*   cu   = (const int*)  d_in[1];
    const float* cosp = (const float*)d_in[2];
    const float* sinp = (const float*)d_in[3];
    const float* Wq   = (const float*)d_in[4];
    const float* bq   = (const float*)d_in[5];
    const float* Wk   = (const float*)d_in[6];
    const float* bk   = (const float*)d_in[7];
    const float* Wv   = (const float*)d_in[8];
    const float* bv   = (const float*)d_in[9];
    const float* Wo   = (const float*)d_in[10];
    const float* bo   = (const float*)d_in[11];
    float* out = (float*)d_out;

    float *part, *attn, *hsr, *wr, *qf, *kf, *vf;
    cudaGetSymbolAddress((void**)&part, g_part);
    cudaGetSymbolAddress((void**)&attn, g_attn);
    cudaGetSymbolAddress((void**)&hsr, g_hsr);
    cudaGetSymbolAddress((void**)&wr, g_wr);
    cudaGetSymbolAddress((void**)&qf, g_qf);
    cudaGetSymbolAddress((void**)&kf, g_kf);
    cudaGetSymbolAddress((void**)&vf, g_vf);
    float* wqr = wr;
    float* wkr = wr + (size_t)D_DIM * D_DIM;
    float* wvr = wr + 2 * (size_t)D_DIM * D_DIM;
    float* wor = wr + 3 * (size_t)D_DIM * D_DIM;

    // pre-round hs + weights (grid x sized for the LARGEST segment: hs)
    int n4hs = TD / 4;
    dim3 rgrid((n4hs + 255) / 256, 5);
    round_tf32_kernel<<<rgrid, 256>>>(hs, Wq, Wk, Wv, Wo);

    cudaFuncSetAttribute(gemm_cp_tf32,
                         cudaFuncAttributeMaxDynamicSharedMemorySize, GEMM_SMEM);

    // fused QKV, split-K x2: z = proj*2 + half -> g_part slots 0..5
    dim3 qkv_grid(D_DIM / BN, T_TOK / BM, 6);   // (9, 8, 6)
    gemm_cp_tf32<<<qkv_grid, 256, GEMM_SMEM>>>(hsr, wqr, wkr, wvr, part);

    // finalize q/k/v: partial sums + bias (+rope/scale), tf32-rounded
    dim3 fgrid((TD / 4 + 255) / 256, 2);
    finalize_qkv<<<fgrid, 256>>>(
        part + 0 * (size_t)TD, part + 1 * (size_t)TD,
        part + 2 * (size_t)TD, part + 3 * (size_t)TD,
        part + 4 * (size_t)TD, part + 5 * (size_t)TD,
        bq, bk, bv, cosp, sinp);

    // attention on finalized q/k/v with cp.async double-buffered K/V
    cudaFuncSetAttribute(attn_kernel,
                         cudaFuncAttributeMaxDynamicSharedMemorySize, ATTN_SMEM);
    attn_kernel<<<dim3(T_TOK / QT, H_NUM), 256, ATTN_SMEM>>>(qf, kf, vf, cu, attn);

    // O projection, split-K x2 -> slots 6,7
    dim3 o_grid(D_DIM / BN, T_TOK / BM, 2);     // (9, 8, 2)
    gemm_cp_tf32<<<o_grid, 256, GEMM_SMEM>>>(attn, wor, wor, wor, part + 6 * (size_t)TD);

    // final reduction: out = p6 + p7 + bo
    reduce_out_kernel<<<(TD / 4 + 255) / 256, 256>>>(
        part + 6 * (size_t)TD, part + 7 * (size_t)TD, bo, out);
}

// round 16
// speedup vs baseline: 1.4140x; 1.0515x over previous
#include <cuda_runtime.h>
#include <cuda_bf16.h>
#include <cstdint>
#include <math.h>

#define T_TOK 2048
#define D_DIM 1152
#define H_NUM 16
#define DH 72
#define NCU 9
#define TD (T_TOK * D_DIM)

// ---------------- scratch (no allocations allowed) ----------------
// g_part slots: 0,1=q halves; 2,3=k; 4,5=v; 6,7=o-proj partials
__device__ float g_part[8][TD];
__device__ float g_attn[TD];
__device__ float g_hsr[TD];
__device__ float g_wr[4][D_DIM * D_DIM];
__device__ float g_qf[TD];   // finalized q (sum+bias+rope+scale, tf32)
__device__ float g_kf[TD];   // finalized k
__device__ float g_vf[TD];   // finalized v

__device__ __forceinline__ float to_tf32(float x) {
    float y; asm("cvt.rna.tf32.f32 %0, %1;" : "=f"(y) : "f"(x)); return y;
}

__device__ __forceinline__ uint32_t smem_u32(const void* p) {
    uint32_t a;
    asm("{ .reg .u64 t; cvta.to.shared.u64 t, %1; cvt.u32.u64 %0, t; }" : "=r"(a) : "l"(p));
    return a;
}
__device__ __forceinline__ void cp16(uint32_t s, const void* g) {
    asm volatile("cp.async.ca.shared.global [%0], [%1], 16;" :: "r"(s), "l"(g));
}
#define CP_COMMIT() asm volatile("cp.async.commit_group;" ::: "memory")
#define CP_WAIT(n)  asm volatile("cp.async.wait_group %0;" :: "n"(n) : "memory")

__device__ __forceinline__ void mma_tf32(float& d0, float& d1, float& d2, float& d3,
                                         uint32_t a0, uint32_t a1, uint32_t a2, uint32_t a3,
                                         uint32_t b0, uint32_t b1) {
    asm volatile(
        "mma.sync.aligned.m16n8k8.row.col.f32.tf32.tf32.f32 "
        "{%0,%1,%2,%3}, {%4,%5,%6,%7}, {%8,%9}, {%0,%1,%2,%3};"
        : "+f"(d0), "+f"(d1), "+f"(d2), "+f"(d3)
        : "r"(a0), "r"(a1), "r"(a2), "r"(a3), "r"(b0), "r"(b1));
}

// ---------------- pre-round pass: tf32-round hs + 4 weights ----------------
__global__ void round_tf32_kernel(const float* __restrict__ hs,
                                  const float* __restrict__ wq, const float* __restrict__ wk,
                                  const float* __restrict__ wv, const float* __restrict__ wo)
{
    const int seg = blockIdx.y;
    const float* src;
    float* dst;
    int n4;
    if (seg == 0) { src = hs; dst = g_hsr;   n4 = TD / 4; }
    else {
        const float* ws[4] = {wq, wk, wv, wo};
        src = ws[seg - 1]; dst = g_wr[seg - 1]; n4 = D_DIM * D_DIM / 4;
    }
    int idx = blockIdx.x * blockDim.x + threadIdx.x;
    if (idx >= n4) return;
    float4 v = ((const float4*)src)[idx];
    v.x = to_tf32(v.x); v.y = to_tf32(v.y); v.z = to_tf32(v.z); v.w = to_tf32(v.w);
    ((float4*)dst)[idx] = v;
}

// ============ cp.async 3-stage split-K tf32 GEMM: Cpart = A @ W^T (half K) ============
// CTA tile 256x128, 8 warps 4x2, warp tile 64x64. KCH=32 (4 ksteps per chunk).
#define BM 256
#define BN 128
#define KCH 32
#define KHALF 576
#define NCHUNK_H (KHALF / KCH)   // 18
#define SPAD 36
#define STAGES 3
#define A_STG (BM * SPAD)        // 9216 floats
#define B_STG (BN * SPAD)        // 4608 floats
#define GEMM_SMEM (STAGES * (A_STG + B_STG) * 4)   // 165888 bytes

__global__ __launch_bounds__(256) void gemm_cp_tf32(
    const float* __restrict__ A,
    const float* __restrict__ W0, const float* __restrict__ W1, const float* __restrict__ W2,
    float* __restrict__ Cbase)
{
    extern __shared__ float smemf[];
    float* sA = smemf;
    float* sB = smemf + STAGES * A_STG;
    const uint32_t uAaddr = smem_u32(sA);
    const uint32_t uBaddr = smem_u32(sB);

    const int z = blockIdx.z;
    const int proj = z >> 1;
    const int koff = (z & 1) * KHALF;
    const float* Bw = (proj == 0) ? W0 : (proj == 1) ? W1 : W2;
    float* C = Cbase + (size_t)z * TD;

    const int tid = threadIdx.x;
    const int wid = tid >> 5;
    const int lane = tid & 31;
    const int gid = lane >> 2;
    const int tig = lane & 3;
    const int wm = wid & 3;
    const int wn = wid >> 2;

    const int bm = blockIdx.y * BM;
    const int bn = blockIdx.x * BN;

    auto issue = [&](int c, int stg) {
#pragma unroll
        for (int i = 0; i < 8; i++) {
            int idx = i * 256 + tid;
            int row = idx >> 3;
            int c4 = (idx & 7) * 4;
            uint32_t off = (uint32_t)(stg * A_STG + row * SPAD + c4) * 4u;
            cp16(uAaddr + off, A + (size_t)(bm + row) * D_DIM + koff + c * KCH + c4);
        }
#pragma unroll
        for (int i = 0; i < 4; i++) {
            int idx = i * 256 + tid;
            int row = idx >> 3;
            int c4 = (idx & 7) * 4;
            uint32_t off = (uint32_t)(stg * B_STG + row * SPAD + c4) * 4u;
            cp16(uBaddr + off, Bw + (size_t)(bn + row) * D_DIM + koff + c * KCH + c4);
        }
    };

    float acc[4][8][4];
#pragma unroll
    for (int i = 0; i < 4; i++)
#pragma unroll
        for (int j = 0; j < 8; j++)
#pragma unroll
            for (int r = 0; r < 4; r++) acc[i][j][r] = 0.f;

    issue(0, 0); CP_COMMIT();
    issue(1, 1); CP_COMMIT();

    int stg = 0;
    int wstg = STAGES - 1;
    for (int c = 0; c < NCHUNK_H; c++) {
        CP_WAIT(1);
        __syncthreads();

        const uint32_t* uA = (const uint32_t*)(sA + stg * A_STG);
        const uint32_t* uB = (const uint32_t*)(sB + stg * B_STG);

#pragma unroll
        for (int ks = 0; ks < 4; ks++) {
            const int k0 = ks * 8;
            uint32_t af[4][4], bf[8][2];
#pragma unroll
            for (int ma = 0; ma < 4; ma++) {
                int r0 = (wm * 64 + ma * 16 + gid) * SPAD;
                af[ma][0] = uA[r0 + k0 + tig];
                af[ma][1] = uA[r0 + 8 * SPAD + k0 + tig];
                af[ma][2] = uA[r0 + k0 + tig + 4];
                af[ma][3] = uA[r0 + 8 * SPAD + k0 + tig + 4];
            }
#pragma unroll
            for (int na = 0; na < 8; na++) {
                int r0 = (wn * 64 + na * 8 + gid) * SPAD;
                bf[na][0] = uB[r0 + k0 + tig];
                bf[na][1] = uB[r0 + k0 + tig + 4];
            }
#pragma unroll
            for (int ma = 0; ma < 4; ma++)
#pragma unroll
                for (int na = 0; na < 8; na++)
                    mma_tf32(acc[ma][na][0], acc[ma][na][1], acc[ma][na][2], acc[ma][na][3],
                             af[ma][0], af[ma][1], af[ma][2], af[ma][3],
                             bf[na][0], bf[na][1]);
        }

        if (c + 2 < NCHUNK_H) issue(c + 2, wstg);
        CP_COMMIT();
        if (++stg == STAGES) stg = 0;
        if (++wstg == STAGES) wstg = 0;
    }

#pragma unroll
    for (int ma = 0; ma < 4; ma++) {
        int row = bm + wm * 64 + ma * 16 + gid;
#pragma unroll
        for (int na = 0; na < 8; na++) {
            int col = bn + wn * 64 + na * 8 + tig * 2;
            *(float2*)(C + (size_t)row * D_DIM + col) = make_float2(acc[ma][na][0], acc[ma][na][1]);
            *(float2*)(C + (size_t)(row + 8) * D_DIM + col) = make_float2(acc[ma][na][2], acc[ma][na][3]);
        }
    }
}

// ---------------- finalize QKV: sum partials + bias (+rope/scale for q,k), tf32 ----------------
__global__ void finalize_qkv(const float* pq0, const float* pq1,
                             const float* pk0, const float* pk1,
                             const float* pv0, const float* pv1,
                             const float* bq, const float* bk, const float* bv,
                             const float* cosp, const float* sinp)
{
    const float scale = rsqrtf((float)DH);
    int idx = blockIdx.x * blockDim.x + threadIdx.x;
    if (blockIdx.y == 0) {
        if (idx >= T_TOK * H_NUM * 9) return;
        int c4 = (idx % 9) * 4;
        int th = idx / 9;
        int h = th % H_NUM;
        int t = th / H_NUM;
        size_t base = (size_t)t * D_DIM + h * DH;
        float4 cc = *(const float4*)(cosp + (size_t)t * DH + c4);
        float4 ss = *(const float4*)(sinp + (size_t)t * DH + c4);

        // q
        {
            float4 a1 = *(const float4*)(pq0 + base + c4);
            float4 b1 = *(const float4*)(pq1 + base + c4);
            float4 a2 = *(const float4*)(pq0 + base + c4 + 36);
            float4 b2 = *(const float4*)(pq1 + base + c4 + 36);
            float4 g1 = *(const float4*)(bq + h * DH + c4);
            float4 g2 = *(const float4*)(bq + h * DH + c4 + 36);
            float4 x1, x2;
            x1.x = a1.x + b1.x + g1.x; x1.y = a1.y + b1.y + g1.y;
            x1.z = a1.z + b1.z + g1.z; x1.w = a1.w + b1.w + g1.w;
            x2.x = a2.x + b2.x + g2.x; x2.y = a2.y + b2.y + g2.y;
            x2.z = a2.z + b2.z + g2.z; x2.w = a2.w + b2.w + g2.w;
            float4 o1, o2;
            o1.x = to_tf32((x1.x * cc.x - x2.x * ss.x) * scale);
            o1.y = to_tf32((x1.y * cc.y - x2.y * ss.y) * scale);
            o1.z = to_tf32((x1.z * cc.z - x2.z * ss.z) * scale);
            o1.w = to_tf32((x1.w * cc.w - x2.w * ss.w) * scale);
            o2.x = to_tf32((x2.x * cc.x + x1.x * ss.x) * scale);
            o2.y = to_tf32((x2.y * cc.y + x1.y * ss.y) * scale);
            o2.z = to_tf32((x2.z * cc.z + x1.z * ss.z) * scale);
            o2.w = to_tf32((x2.w * cc.w + x1.w * ss.w) * scale);
            *(float4*)(g_qf + base + c4) = o1;
            *(float4*)(g_qf + base + c4 + 36) = o2;
        }
        // k (no scale)
        {
            float4 a1 = *(const float4*)(pk0 + base + c4);
            float4 b1 = *(const float4*)(pk1 + base + c4);
            float4 a2 = *(const float4*)(pk0 + base + c4 + 36);
            float4 b2 = *(const float4*)(pk1 + base + c4 + 36);
            float4 g1 = *(const float4*)(bk + h * DH + c4);
            float4 g2 = *(const float4*)(bk + h * DH + c4 + 36);
            float4 x1, x2;
            x1.x = a1.x + b1.x + g1.x; x1.y = a1.y + b1.y + g1.y;
            x1.z = a1.z + b1.z + g1.z; x1.w = a1.w + b1.w + g1.w;
            x2.x = a2.x + b2.x + g2.x; x2.y = a2.y + b2.y + g2.y;
            x2.z = a2.z + b2.z + g2.z; x2.w = a2.w + b2.w + g2.w;
            float4 o1, o2;
            o1.x = to_tf32(x1.x * cc.x - x2.x * ss.x);
            o1.y = to_tf32(x1.y * cc.y - x2.y * ss.y);
            o1.z = to_tf32(x1.z * cc.z - x2.z * ss.z);
            o1.w = to_tf32(x1.w * cc.w - x2.w * ss.w);
            o2.x = to_tf32(x2.x * cc.x + x1.x * ss.x);
            o2.y = to_tf32(x2.y * cc.y + x1.y * ss.y);
            o2.z = to_tf32(x2.z * cc.z + x1.z * ss.z);
            o2.w = to_tf32(x2.w * cc.w + x1.w * ss.w);
            *(float4*)(g_kf + base + c4) = o1;
            *(float4*)(g_kf + base + c4 + 36) = o2;
        }
    } else {
        if (idx >= TD / 4) return;
        int col = (idx * 4) % D_DIM;
        float4 a = ((const float4*)pv0)[idx];
        float4 b = ((const float4*)pv1)[idx];
        float4 g = *(const float4*)(bv + col);
        float4 o;
        o.x = to_tf32(a.x + b.x + g.x);
        o.y = to_tf32(a.y + b.y + g.y);
        o.z = to_tf32(a.z + b.z + g.z);
        o.w = to_tf32(a.w + b.w + g.w);
        ((float4*)g_vf)[idx] = o;
    }
}

// ---------------- O-projection reduction: out = p6 + p7 + bo ----------------
__global__ void reduce_out_kernel(const float* __restrict__ p0, const float* __restrict__ p1,
                                  const float* __restrict__ bo, float* __restrict__ out)
{
    int idx = blockIdx.x * blockDim.x + threadIdx.x;
    if (idx >= TD / 4) return;
    int col = (idx * 4) % D_DIM;
    float4 a = ((const float4*)p0)[idx];
    float4 b = ((const float4*)p1)[idx];
    float4 bb = *(const float4*)(bo + col);
    float4 o;
    o.x = a.x + b.x + bb.x;
    o.y = a.y + b.y + bb.y;
    o.z = a.z + b.z + bb.z;
    o.w = a.w + b.w + bb.w;
    ((float4*)out)[idx] = o;
}

// ---------------- Segment-masked flash attention (tf32 mma.sync, 2 CTAs/SM) ----------------
// grid (T/128, H), 256 threads (8 warps x 16 query rows). K-tile 64, SINGLE buffer
// (smem 111.6KB -> 2 CTAs/SM; inter-CTA overlap hides the serial softmax chain).
#define QT 128
#define KT 64
#define QK_STRIDE 76
#define V_STRIDE 72
#define P_STRIDE 68
#define SQ_FLOATS (QT * QK_STRIDE)            // 9728
#define SK_FLOATS (KT * QK_STRIDE)            // 4864
#define SV_FLOATS (KT * V_STRIDE)             // 4608
#define SP_FLOATS (QT * P_STRIDE)             // 8704
#define ATTN_SMEM ((SQ_FLOATS + SK_FLOATS + SV_FLOATS + SP_FLOATS) * 4)  // 111616

__global__ __launch_bounds__(256, 2) void attn_kernel(
    const float* __restrict__ qf, const float* __restrict__ kf,
    const float* __restrict__ vf, const int* __restrict__ cu,
    float* __restrict__ out)
{
    extern __shared__ float smemf[];
    float* sQ = smemf;                             // 128 x 76
    float* sK = sQ + SQ_FLOATS;                    // 64 x 76
    float* sV = sK + SK_FLOATS;                    // 64 x 72
    float* sP = sV + SV_FLOATS;                    // 128 x 68
    __shared__ int sCu[NCU];
    __shared__ int sSegQ[QT];
    __shared__ int sSegK[KT];

    const uint32_t uKaddr = smem_u32(sK);
    const uint32_t uVaddr = smem_u32(sV);

    const int tid = threadIdx.x;
    const int wid = tid >> 5;
    const int lane = tid & 31;
    const int gid = lane >> 2;
    const int tig = lane & 3;
    const int h = blockIdx.y;
    const int q0 = blockIdx.x * QT;

    if (tid < NCU) sCu[tid] = cu[tid];
    __syncthreads();

    // ---- load Q (pre-finalized): 128 rows x 18 float4 ----
    for (int i = tid; i < QT * 18; i += 256) {
        int r = i / 18, c4 = (i % 18) * 4;
        *(float4*)(&sQ[r * QK_STRIDE + c4]) =
            *(const float4*)(qf + (size_t)(q0 + r) * D_DIM + h * DH + c4);
    }
    if (tid < QT) {
        int t = q0 + tid;
        int s = 0;
#pragma unroll
        for (int j = 1; j < NCU; j++)
            if (sCu[j] <= t) s = j;
        sSegQ[tid] = s;
    }
    __syncthreads();

    const int seg_lo = sSegQ[0];
    const int seg_hi = sSegQ[QT - 1];
    const int k_end = sCu[seg_hi + 1];
    const int kc0 = (sCu[seg_lo] / KT) * KT;

    const int r0 = wid * 16 + gid;
    const int segq0 = sSegQ[r0];
    const int segq1 = sSegQ[r0 + 8];

    // cp.async loader for one K/V tile: 2304 float4, 9 per thread
    auto issue_kv = [&](int kc) {
#pragma unroll
        for (int i = 0; i < 9; i++) {
            int idx = i * 256 + tid;
            if (idx < KT * 18) {
                int row = idx / 18, c4 = (idx % 18) * 4;
                cp16(uKaddr + (uint32_t)(row * QK_STRIDE + c4) * 4u,
                     kf + (size_t)(kc + row) * D_DIM + h * DH + c4);
            } else {
                int j = idx - KT * 18;
                int row = j / 18, c4 = (j % 18) * 4;
                cp16(uVaddr + (uint32_t)(row * V_STRIDE + c4) * 4u,
                     vf + (size_t)(kc + row) * D_DIM + h * DH + c4);
            }
        }
    };

    float m0 = -1e30f, m1 = -1e30f, l0 = 0.f, l1 = 0.f;
    float O[9][4];
#pragma unroll
    for (int no = 0; no < 9; no++)
#pragma unroll
        for (int r = 0; r < 4; r++) O[no][r] = 0.f;

    const uint32_t* uQ = (const uint32_t*)sQ;
    const uint32_t* uP = (const uint32_t*)sP;
    const uint32_t* uK = (const uint32_t*)sK;
    const uint32_t* uV = (const uint32_t*)sV;

    for (int kc = kc0; kc < k_end; kc += KT) {
        // protect K/V (+segK) from previous tile's readers, then load this tile
        __syncthreads();
        issue_kv(kc); CP_COMMIT();
        if (tid < KT) {
            int t = kc + tid;
            int s = 0;
#pragma unroll
            for (int j = 1; j < NCU; j++)
                if (sCu[j] <= t) s = j;
            sSegK[tid] = s;
        }
        CP_WAIT(0);
        __syncthreads();

        // ---- S = Q K^T ----
        float accS[8][4];
#pragma unroll
        for (int na = 0; na < 8; na++)
#pragma unroll
            for (int r = 0; r < 4; r++) accS[na][r] = 0.f;

#pragma unroll
        for (int ks = 0; ks < 9; ks++) {
            const int k0 = ks * 8;
            uint32_t a0 = uQ[r0 * QK_STRIDE + k0 + tig];
            uint32_t a1 = uQ[(r0 + 8) * QK_STRIDE + k0 + tig];
            uint32_t a2 = uQ[r0 * QK_STRIDE + k0 + tig + 4];
            uint32_t a3 = uQ[(r0 + 8) * QK_STRIDE + k0 + tig + 4];
#pragma unroll
            for (int na = 0; na < 8; na++) {
                uint32_t b0 = uK[(na * 8 + gid) * QK_STRIDE + k0 + tig];
                uint32_t b1 = uK[(na * 8 + gid) * QK_STRIDE + k0 + tig + 4];
                mma_tf32(accS[na][0], accS[na][1], accS[na][2], accS[na][3],
                         a0, a1, a2, a3, b0, b1);
            }
        }

        // ---- mask ----
#pragma unroll
        for (int na = 0; na < 8; na++) {
            int c0 = na * 8 + tig * 2;
            int sk0 = sSegK[c0], sk1 = sSegK[c0 + 1];
            if (sk0 != segq0) accS[na][0] = -1e30f;
            if (sk1 != segq0) accS[na][1] = -1e30f;
            if (sk0 != segq1) accS[na][2] = -1e30f;
            if (sk1 != segq1) accS[na][3] = -1e30f;
        }

        // ---- online softmax ----
        float mt0 = -1e30f, mt1 = -1e30f;
#pragma unroll
        for (int na = 0; na < 8; na++) {
            mt0 = fmaxf(mt0, fmaxf(accS[na][0], accS[na][1]));
            mt1 = fmaxf(mt1, fmaxf(accS[na][2], accS[na][3]));
        }
        mt0 = fmaxf(mt0, __shfl_xor_sync(0xffffffffu, mt0, 1));
        mt0 = fmaxf(mt0, __shfl_xor_sync(0xffffffffu, mt0, 2));
        mt1 = fmaxf(mt1, __shfl_xor_sync(0xffffffffu, mt1, 1));
        mt1 = fmaxf(mt1, __shfl_xor_sync(0xffffffffu, mt1, 2));
        float mn0 = fmaxf(m0, mt0);
        float mn1 = fmaxf(m1, mt1);

        float ls0 = 0.f, ls1 = 0.f;
#pragma unroll
        for (int na = 0; na < 8; na++) {
            float p00 = (accS[na][0] < -1e29f) ? 0.f : to_tf32(__expf(accS[na][0] - mn0));
            float p01 = (accS[na][1] < -1e29f) ? 0.f : to_tf32(__expf(accS[na][1] - mn0));
            float p10 = (accS[na][2] < -1e29f) ? 0.f : to_tf32(__expf(accS[na][2] - mn1));
            float p11 = (accS[na][3] < -1e29f) ? 0.f : to_tf32(__expf(accS[na][3] - mn1));
            ls0 += p00 + p01;
            ls1 += p10 + p11;
            int c0 = na * 8 + tig * 2;
            *(float2*)(&sP[r0 * P_STRIDE + c0]) = make_float2(p00, p01);
            *(float2*)(&sP[(r0 + 8) * P_STRIDE + c0]) = make_float2(p10, p11);
        }
        ls0 += __shfl_xor_sync(0xffffffffu, ls0, 1);
        ls0 += __shfl_xor_sync(0xffffffffu, ls0, 2);
        ls1 += __shfl_xor_sync(0xffffffffu, ls1, 1);
        ls1 += __shfl_xor_sync(0xffffffffu, ls1, 2);

        float al0 = __expf(m0 - mn0);
        float al1 = __expf(m1 - mn1);
        l0 = l0 * al0 + ls0;
        l1 = l1 * al1 + ls1;
        m0 = mn0; m1 = mn1;

#pragma unroll
        for (int no = 0; no < 9; no++) {
            O[no][0] *= al0; O[no][1] *= al0;
            O[no][2] *= al1; O[no][3] *= al1;
        }
        __syncwarp();

        // ---- O += P V ----
#pragma unroll
        for (int ks = 0; ks < 8; ks++) {
            const int k0 = ks * 8;
            uint32_t a0 = uP[r0 * P_STRIDE + k0 + tig];
            uint32_t a1 = uP[(r0 + 8) * P_STRIDE + k0 + tig];
            uint32_t a2 = uP[r0 * P_STRIDE + k0 + tig + 4];
            uint32_t a3 = uP[(r0 + 8) * P_STRIDE + k0 + tig + 4];
#pragma unroll
            for (int no = 0; no < 9; no++) {
                uint32_t b0 = uV[(k0 + tig) * V_STRIDE + no * 8 + gid];
                uint32_t b1 = uV[(k0 + tig + 4) * V_STRIDE + no * 8 + gid];
                mma_tf32(O[no][0], O[no][1], O[no][2], O[no][3],
                         a0, a1, a2, a3, b0, b1);
            }
        }
    }

    float il0 = 1.f / l0;
    float il1 = 1.f / l1;
    size_t ob0 = (size_t)(q0 + r0) * D_DIM + h * DH;
    size_t ob1 = (size_t)(q0 + r0 + 8) * D_DIM + h * DH;
#pragma unroll
    for (int no = 0; no < 9; no++) {
        int c0 = no * 8 + tig * 2;
        *(float2*)(out + ob0 + c0) = make_float2(to_tf32(O[no][0] * il0), to_tf32(O[no][1] * il0));
        *(float2*)(out + ob1 + c0) = make_float2(to_tf32(O[no][2] * il1), to_tf32(O[no][3] * il1));
    }
}

// ---------------- host launch ----------------
extern "C" void kernel_launch(void* const* d_in, const int* in_sizes, int n_in,
                              void* d_out, int out_size)
{
    const float* hs   = (const float*)d_in[0];
    const int*   cu   = (const int*)  d_in[1];
    const float* cosp = (const float*)d_in[2];
    const float* sinp = (const float*)d_in[3];
    const float* Wq   = (const float*)d_in[4];
    const float* bq   = (const float*)d_in[5];
    const float* Wk   = (const float*)d_in[6];
    const float* bk   = (const float*)d_in[7];
    const float* Wv   = (const float*)d_in[8];
    const float* bv   = (const float*)d_in[9];
    const float* Wo   = (const float*)d_in[10];
    const float* bo   = (const float*)d_in[11];
    float* out = (float*)d_out;

    float *part, *attn, *hsr, *wr, *qf, *kf, *vf;
    cudaGetSymbolAddress((void**)&part, g_part);
    cudaGetSymbolAddress((void**)&attn, g_attn);
    cudaGetSymbolAddress((void**)&hsr, g_hsr);
    cudaGetSymbolAddress((void**)&wr, g_wr);
    cudaGetSymbolAddress((void**)&qf, g_qf);
    cudaGetSymbolAddress((void**)&kf, g_kf);
    cudaGetSymbolAddress((void**)&vf, g_vf);
    float* wqr = wr;
    float* wkr = wr + (size_t)D_DIM * D_DIM;
    float* wvr = wr + 2 * (size_t)D_DIM * D_DIM;
    float* wor = wr + 3 * (size_t)D_DIM * D_DIM;

    // pre-round hs + weights (grid x sized for the LARGEST segment: hs)
    int n4hs = TD / 4;
    dim3 rgrid((n4hs + 255) / 256, 5);
    round_tf32_kernel<<<rgrid, 256>>>(hs, Wq, Wk, Wv, Wo);

    cudaFuncSetAttribute(gemm_cp_tf32,
                         cudaFuncAttributeMaxDynamicSharedMemorySize, GEMM_SMEM);

    // fused QKV, split-K x2: z = proj*2 + half -> g_part slots 0..5
    dim3 qkv_grid(D_DIM / BN, T_TOK / BM, 6);   // (9, 8, 6)
    gemm_cp_tf32<<<qkv_grid, 256, GEMM_SMEM>>>(hsr, wqr, wkr, wvr, part);

    // finalize q/k/v: partial sums + bias (+rope/scale), tf32-rounded
    dim3 fgrid((TD / 4 + 255) / 256, 2);
    finalize_qkv<<<fgrid, 256>>>(
        part + 0 * (size_t)TD, part + 1 * (size_t)TD,
        part + 2 * (size_t)TD, part + 3 * (size_t)TD,
        part + 4 * (size_t)TD, part + 5 * (size_t)TD,
        bq, bk, bv, cosp, sinp);

    // attention on finalized q/k/v (2 CTAs/SM)
    cudaFuncSetAttribute(attn_kernel,
                         cudaFuncAttributeMaxDynamicSharedMemorySize, ATTN_SMEM);
    attn_kernel<<<dim3(T_TOK / QT, H_NUM), 256, ATTN_SMEM>>>(qf, kf, vf, cu, attn);

    // O projection, split-K x2 -> slots 6,7
    dim3 o_grid(D_DIM / BN, T_TOK / BM, 2);     // (9, 8, 2)
    gemm_cp_tf32<<<o_grid, 256, GEMM_SMEM>>>(attn, wor, wor, wor, part + 6 * (size_t)TD);

    // final reduction: out = p6 + p7 + bo
    reduce_out_kernel<<<(TD / 4 + 255) / 256, 256>>>(
        part + 6 * (size_t)TD, part + 7 * (size_t)TD, bo, out);
}

// round 17
// speedup vs baseline: 1.4247x; 1.0075x over previous
#include <cuda_runtime.h>
#include <cuda_bf16.h>
#include <cstdint>
#include <math.h>

#define T_TOK 2048
#define D_DIM 1152
#define H_NUM 16
#define DH 72
#define NCU 9
#define TD (T_TOK * D_DIM)

// ---------------- scratch (no allocations allowed) ----------------
// g_part slots: 0,1=q halves; 2,3=k; 4,5=v; 6,7=o-proj partials
__device__ float g_part[8][TD];
__device__ float g_attn[TD];
__device__ float g_hsr[TD];
__device__ float g_wr[4][D_DIM * D_DIM];
__device__ float g_qf[TD];   // finalized q (sum+bias+rope+scale, tf32)
__device__ float g_kf[TD];   // finalized k
__device__ float g_vf[TD];   // finalized v

__device__ __forceinline__ float to_tf32(float x) {
    float y; asm("cvt.rna.tf32.f32 %0, %1;" : "=f"(y) : "f"(x)); return y;
}

__device__ __forceinline__ uint32_t smem_u32(const void* p) {
    uint32_t a;
    asm("{ .reg .u64 t; cvta.to.shared.u64 t, %1; cvt.u32.u64 %0, t; }" : "=r"(a) : "l"(p));
    return a;
}
__device__ __forceinline__ void cp16(uint32_t s, const void* g) {
    asm volatile("cp.async.ca.shared.global [%0], [%1], 16;" :: "r"(s), "l"(g));
}
#define CP_COMMIT() asm volatile("cp.async.commit_group;" ::: "memory")
#define CP_WAIT(n)  asm volatile("cp.async.wait_group %0;" :: "n"(n) : "memory")

__device__ __forceinline__ void mma_tf32(float& d0, float& d1, float& d2, float& d3,
                                         uint32_t a0, uint32_t a1, uint32_t a2, uint32_t a3,
                                         uint32_t b0, uint32_t b1) {
    asm volatile(
        "mma.sync.aligned.m16n8k8.row.col.f32.tf32.tf32.f32 "
        "{%0,%1,%2,%3}, {%4,%5,%6,%7}, {%8,%9}, {%0,%1,%2,%3};"
        : "+f"(d0), "+f"(d1), "+f"(d2), "+f"(d3)
        : "r"(a0), "r"(a1), "r"(a2), "r"(a3), "r"(b0), "r"(b1));
}

// ---------------- pre-round pass: tf32-round hs + 4 weights ----------------
__global__ void round_tf32_kernel(const float* __restrict__ hs,
                                  const float* __restrict__ wq, const float* __restrict__ wk,
                                  const float* __restrict__ wv, const float* __restrict__ wo)
{
    const int seg = blockIdx.y;
    const float* src;
    float* dst;
    int n4;
    if (seg == 0) { src = hs; dst = g_hsr;   n4 = TD / 4; }
    else {
        const float* ws[4] = {wq, wk, wv, wo};
        src = ws[seg - 1]; dst = g_wr[seg - 1]; n4 = D_DIM * D_DIM / 4;
    }
    int idx = blockIdx.x * blockDim.x + threadIdx.x;
    if (idx >= n4) return;
    float4 v = ((const float4*)src)[idx];
    v.x = to_tf32(v.x); v.y = to_tf32(v.y); v.z = to_tf32(v.z); v.w = to_tf32(v.w);
    ((float4*)dst)[idx] = v;
}

// ============ cp.async 3-stage split-K tf32 GEMM: Cpart = A @ W^T (half K) ============
// CTA tile 256x128, 8 warps 4x2, warp tile 64x64. KCH=32 (4 ksteps per chunk).
#define BM 256
#define BN 128
#define KCH 32
#define KHALF 576
#define NCHUNK_H (KHALF / KCH)   // 18
#define SPAD 36
#define STAGES 3
#define A_STG (BM * SPAD)        // 9216 floats
#define B_STG (BN * SPAD)        // 4608 floats
#define GEMM_SMEM (STAGES * (A_STG + B_STG) * 4)   // 165888 bytes

__global__ __launch_bounds__(256) void gemm_cp_tf32(
    const float* __restrict__ A,
    const float* __restrict__ W0, const float* __restrict__ W1, const float* __restrict__ W2,
    float* __restrict__ Cbase)
{
    extern __shared__ float smemf[];
    float* sA = smemf;
    float* sB = smemf + STAGES * A_STG;
    const uint32_t uAaddr = smem_u32(sA);
    const uint32_t uBaddr = smem_u32(sB);

    const int z = blockIdx.z;
    const int proj = z >> 1;
    const int koff = (z & 1) * KHALF;
    const float* Bw = (proj == 0) ? W0 : (proj == 1) ? W1 : W2;
    float* C = Cbase + (size_t)z * TD;

    const int tid = threadIdx.x;
    const int wid = tid >> 5;
    const int lane = tid & 31;
    const int gid = lane >> 2;
    const int tig = lane & 3;
    const int wm = wid & 3;
    const int wn = wid >> 2;

    const int bm = blockIdx.y * BM;
    const int bn = blockIdx.x * BN;

    auto issue = [&](int c, int stg) {
#pragma unroll
        for (int i = 0; i < 8; i++) {
            int idx = i * 256 + tid;
            int row = idx >> 3;
            int c4 = (idx & 7) * 4;
            uint32_t off = (uint32_t)(stg * A_STG + row * SPAD + c4) * 4u;
            cp16(uAaddr + off, A + (size_t)(bm + row) * D_DIM + koff + c * KCH + c4);
        }
#pragma unroll
        for (int i = 0; i < 4; i++) {
            int idx = i * 256 + tid;
            int row = idx >> 3;
            int c4 = (idx & 7) * 4;
            uint32_t off = (uint32_t)(stg * B_STG + row * SPAD + c4) * 4u;
            cp16(uBaddr + off, Bw + (size_t)(bn + row) * D_DIM + koff + c * KCH + c4);
        }
    };

    float acc[4][8][4];
#pragma unroll
    for (int i = 0; i < 4; i++)
#pragma unroll
        for (int j = 0; j < 8; j++)
#pragma unroll
            for (int r = 0; r < 4; r++) acc[i][j][r] = 0.f;

    issue(0, 0); CP_COMMIT();
    issue(1, 1); CP_COMMIT();

    int stg = 0;
    int wstg = STAGES - 1;
    for (int c = 0; c < NCHUNK_H; c++) {
        CP_WAIT(1);
        __syncthreads();

        const uint32_t* uA = (const uint32_t*)(sA + stg * A_STG);
        const uint32_t* uB = (const uint32_t*)(sB + stg * B_STG);

#pragma unroll
        for (int ks = 0; ks < 4; ks++) {
            const int k0 = ks * 8;
            uint32_t af[4][4], bf[8][2];
#pragma unroll
            for (int ma = 0; ma < 4; ma++) {
                int r0 = (wm * 64 + ma * 16 + gid) * SPAD;
                af[ma][0] = uA[r0 + k0 + tig];
                af[ma][1] = uA[r0 + 8 * SPAD + k0 + tig];
                af[ma][2] = uA[r0 + k0 + tig + 4];
                af[ma][3] = uA[r0 + 8 * SPAD + k0 + tig + 4];
            }
#pragma unroll
            for (int na = 0; na < 8; na++) {
                int r0 = (wn * 64 + na * 8 + gid) * SPAD;
                bf[na][0] = uB[r0 + k0 + tig];
                bf[na][1] = uB[r0 + k0 + tig + 4];
            }
#pragma unroll
            for (int ma = 0; ma < 4; ma++)
#pragma unroll
                for (int na = 0; na < 8; na++)
                    mma_tf32(acc[ma][na][0], acc[ma][na][1], acc[ma][na][2], acc[ma][na][3],
                             af[ma][0], af[ma][1], af[ma][2], af[ma][3],
                             bf[na][0], bf[na][1]);
        }

        if (c + 2 < NCHUNK_H) issue(c + 2, wstg);
        CP_COMMIT();
        if (++stg == STAGES) stg = 0;
        if (++wstg == STAGES) wstg = 0;
    }

#pragma unroll
    for (int ma = 0; ma < 4; ma++) {
        int row = bm + wm * 64 + ma * 16 + gid;
#pragma unroll
        for (int na = 0; na < 8; na++) {
            int col = bn + wn * 64 + na * 8 + tig * 2;
            *(float2*)(C + (size_t)row * D_DIM + col) = make_float2(acc[ma][na][0], acc[ma][na][1]);
            *(float2*)(C + (size_t)(row + 8) * D_DIM + col) = make_float2(acc[ma][na][2], acc[ma][na][3]);
        }
    }
}

// ---------------- finalize QKV: sum partials + bias (+rope/scale for q,k), tf32 ----------------
__global__ void finalize_qkv(const float* pq0, const float* pq1,
                             const float* pk0, const float* pk1,
                             const float* pv0, const float* pv1,
                             const float* bq, const float* bk, const float* bv,
                             const float* cosp, const float* sinp)
{
    const float scale = rsqrtf((float)DH);
    int idx = blockIdx.x * blockDim.x + threadIdx.x;
    if (blockIdx.y == 0) {
        if (idx >= T_TOK * H_NUM * 9) return;
        int c4 = (idx % 9) * 4;
        int th = idx / 9;
        int h = th % H_NUM;
        int t = th / H_NUM;
        size_t base = (size_t)t * D_DIM + h * DH;
        float4 cc = *(const float4*)(cosp + (size_t)t * DH + c4);
        float4 ss = *(const float4*)(sinp + (size_t)t * DH + c4);

        // q
        {
            float4 a1 = *(const float4*)(pq0 + base + c4);
            float4 b1 = *(const float4*)(pq1 + base + c4);
            float4 a2 = *(const float4*)(pq0 + base + c4 + 36);
            float4 b2 = *(const float4*)(pq1 + base + c4 + 36);
            float4 g1 = *(const float4*)(bq + h * DH + c4);
            float4 g2 = *(const float4*)(bq + h * DH + c4 + 36);
            float4 x1, x2;
            x1.x = a1.x + b1.x + g1.x; x1.y = a1.y + b1.y + g1.y;
            x1.z = a1.z + b1.z + g1.z; x1.w = a1.w + b1.w + g1.w;
            x2.x = a2.x + b2.x + g2.x; x2.y = a2.y + b2.y + g2.y;
            x2.z = a2.z + b2.z + g2.z; x2.w = a2.w + b2.w + g2.w;
            float4 o1, o2;
            o1.x = to_tf32((x1.x * cc.x - x2.x * ss.x) * scale);
            o1.y = to_tf32((x1.y * cc.y - x2.y * ss.y) * scale);
            o1.z = to_tf32((x1.z * cc.z - x2.z * ss.z) * scale);
            o1.w = to_tf32((x1.w * cc.w - x2.w * ss.w) * scale);
            o2.x = to_tf32((x2.x * cc.x + x1.x * ss.x) * scale);
            o2.y = to_tf32((x2.y * cc.y + x1.y * ss.y) * scale);
            o2.z = to_tf32((x2.z * cc.z + x1.z * ss.z) * scale);
            o2.w = to_tf32((x2.w * cc.w + x1.w * ss.w) * scale);
            *(float4*)(g_qf + base + c4) = o1;
            *(float4*)(g_qf + base + c4 + 36) = o2;
        }
        // k (no scale)
        {
            float4 a1 = *(const float4*)(pk0 + base + c4);
            float4 b1 = *(const float4*)(pk1 + base + c4);
            float4 a2 = *(const float4*)(pk0 + base + c4 + 36);
            float4 b2 = *(const float4*)(pk1 + base + c4 + 36);
            float4 g1 = *(const float4*)(bk + h * DH + c4);
            float4 g2 = *(const float4*)(bk + h * DH + c4 + 36);
            float4 x1, x2;
            x1.x = a1.x + b1.x + g1.x; x1.y = a1.y + b1.y + g1.y;
            x1.z = a1.z + b1.z + g1.z; x1.w = a1.w + b1.w + g1.w;
            x2.x = a2.x + b2.x + g2.x; x2.y = a2.y + b2.y + g2.y;
            x2.z = a2.z + b2.z + g2.z; x2.w = a2.w + b2.w + g2.w;
            float4 o1, o2;
            o1.x = to_tf32(x1.x * cc.x - x2.x * ss.x);
            o1.y = to_tf32(x1.y * cc.y - x2.y * ss.y);
            o1.z = to_tf32(x1.z * cc.z - x2.z * ss.z);
            o1.w = to_tf32(x1.w * cc.w - x2.w * ss.w);
            o2.x = to_tf32(x2.x * cc.x + x1.x * ss.x);
            o2.y = to_tf32(x2.y * cc.y + x1.y * ss.y);
            o2.z = to_tf32(x2.z * cc.z + x1.z * ss.z);
            o2.w = to_tf32(x2.w * cc.w + x1.w * ss.w);
            *(float4*)(g_kf + base + c4) = o1;
            *(float4*)(g_kf + base + c4 + 36) = o2;
        }
    } else {
        if (idx >= TD / 4) return;
        int col = (idx * 4) % D_DIM;
        float4 a = ((const float4*)pv0)[idx];
        float4 b = ((const float4*)pv1)[idx];
        float4 g = *(const float4*)(bv + col);
        float4 o;
        o.x = to_tf32(a.x + b.x + g.x);
        o.y = to_tf32(a.y + b.y + g.y);
        o.z = to_tf32(a.z + b.z + g.z);
        o.w = to_tf32(a.w + b.w + g.w);
        ((float4*)g_vf)[idx] = o;
    }
}

// ---------------- O-projection reduction: out = p6 + p7 + bo ----------------
__global__ void reduce_out_kernel(const float* __restrict__ p0, const float* __restrict__ p1,
                                  const float* __restrict__ bo, float* __restrict__ out)
{
    int idx = blockIdx.x * blockDim.x + threadIdx.x;
    if (idx >= TD / 4) return;
    int col = (idx * 4) % D_DIM;
    float4 a = ((const float4*)p0)[idx];
    float4 b = ((const float4*)p1)[idx];
    float4 bb = *(const float4*)(bo + col);
    float4 o;
    o.x = a.x + b.x + bb.x;
    o.y = a.y + b.y + bb.y;
    o.z = a.z + b.z + bb.z;
    o.w = a.w + b.w + bb.w;
    ((float4*)out)[idx] = o;
}

// ---------------- Segment-masked flash attention (tf32 mma.sync, 2 CTAs/SM, warp tile-skip) ----------------
// grid (T/128, H), 256 threads (8 warps x 16 query rows). K-tile 64, single buffer.
// Each warp owns 16 consecutive q-rows; K-tiles disjoint from the warp's segment
// range are skipped entirely (they would be fully masked -> contribute 0).
#define QT 128
#define KT 64
#define QK_STRIDE 76
#define V_STRIDE 72
#define P_STRIDE 68
#define SQ_FLOATS (QT * QK_STRIDE)            // 9728
#define SK_FLOATS (KT * QK_STRIDE)            // 4864
#define SV_FLOATS (KT * V_STRIDE)             // 4608
#define SP_FLOATS (QT * P_STRIDE)             // 8704
#define ATTN_SMEM ((SQ_FLOATS + SK_FLOATS + SV_FLOATS + SP_FLOATS) * 4)  // 111616

__global__ __launch_bounds__(256, 2) void attn_kernel(
    const float* __restrict__ qf, const float* __restrict__ kf,
    const float* __restrict__ vf, const int* __restrict__ cu,
    float* __restrict__ out)
{
    extern __shared__ float smemf[];
    float* sQ = smemf;                             // 128 x 76
    float* sK = sQ + SQ_FLOATS;                    // 64 x 76
    float* sV = sK + SK_FLOATS;                    // 64 x 72
    float* sP = sV + SV_FLOATS;                    // 128 x 68
    __shared__ int sCu[NCU];
    __shared__ int sSegQ[QT];
    __shared__ int sSegK[KT];

    const uint32_t uKaddr = smem_u32(sK);
    const uint32_t uVaddr = smem_u32(sV);

    const int tid = threadIdx.x;
    const int wid = tid >> 5;
    const int lane = tid & 31;
    const int gid = lane >> 2;
    const int tig = lane & 3;
    const int h = blockIdx.y;
    const int q0 = blockIdx.x * QT;

    if (tid < NCU) sCu[tid] = cu[tid];
    __syncthreads();

    // ---- load Q (pre-finalized): 128 rows x 18 float4 ----
    for (int i = tid; i < QT * 18; i += 256) {
        int r = i / 18, c4 = (i % 18) * 4;
        *(float4*)(&sQ[r * QK_STRIDE + c4]) =
            *(const float4*)(qf + (size_t)(q0 + r) * D_DIM + h * DH + c4);
    }
    if (tid < QT) {
        int t = q0 + tid;
        int s = 0;
#pragma unroll
        for (int j = 1; j < NCU; j++)
            if (sCu[j] <= t) s = j;
        sSegQ[tid] = s;
    }
    __syncthreads();

    const int seg_lo = sSegQ[0];
    const int seg_hi = sSegQ[QT - 1];
    const int k_end = sCu[seg_hi + 1];
    const int kc0 = (sCu[seg_lo] / KT) * KT;

    const int r0 = wid * 16 + gid;
    const int segq0 = sSegQ[r0];
    const int segq1 = sSegQ[r0 + 8];

    // warp-level key range: union of segments of this warp's 16 rows
    const int wseg_lo = sSegQ[wid * 16];
    const int wseg_hi = sSegQ[wid * 16 + 15];
    const int wk_start = sCu[wseg_lo];
    const int wk_end = sCu[wseg_hi + 1];

    // cp.async loader for one K/V tile: 2304 float4, 9 per thread
    auto issue_kv = [&](int kc) {
#pragma unroll
        for (int i = 0; i < 9; i++) {
            int idx = i * 256 + tid;
            if (idx < KT * 18) {
                int row = idx / 18, c4 = (idx % 18) * 4;
                cp16(uKaddr + (uint32_t)(row * QK_STRIDE + c4) * 4u,
                     kf + (size_t)(kc + row) * D_DIM + h * DH + c4);
            } else {
                int j = idx - KT * 18;
                int row = j / 18, c4 = (j % 18) * 4;
                cp16(uVaddr + (uint32_t)(row * V_STRIDE + c4) * 4u,
                     vf + (size_t)(kc + row) * D_DIM + h * DH + c4);
            }
        }
    };

    float m0 = -1e30f, m1 = -1e30f, l0 = 0.f, l1 = 0.f;
    float O[9][4];
#pragma unroll
    for (int no = 0; no < 9; no++)
#pragma unroll
        for (int r = 0; r < 4; r++) O[no][r] = 0.f;

    const uint32_t* uQ = (const uint32_t*)sQ;
    const uint32_t* uP = (const uint32_t*)sP;
    const uint32_t* uK = (const uint32_t*)sK;
    const uint32_t* uV = (const uint32_t*)sV;

    for (int kc = kc0; kc < k_end; kc += KT) {
        // protect K/V (+segK) from previous tile's readers, then load this tile
        __syncthreads();
        issue_kv(kc); CP_COMMIT();
        if (tid < KT) {
            int t = kc + tid;
            int s = 0;
#pragma unroll
            for (int j = 1; j < NCU; j++)
                if (sCu[j] <= t) s = j;
            sSegK[tid] = s;
        }
        CP_WAIT(0);
        __syncthreads();

        // warp-level skip: this K-tile is fully masked for all 16 of this warp's rows
        if (kc + KT <= wk_start || kc >= wk_end) continue;

        // ---- S = Q K^T ----
        float accS[8][4];
#pragma unroll
        for (int na = 0; na < 8; na++)
#pragma unroll
            for (int r = 0; r < 4; r++) accS[na][r] = 0.f;

#pragma unroll
        for (int ks = 0; ks < 9; ks++) {
            const int k0 = ks * 8;
            uint32_t a0 = uQ[r0 * QK_STRIDE + k0 + tig];
            uint32_t a1 = uQ[(r0 + 8) * QK_STRIDE + k0 + tig];
            uint32_t a2 = uQ[r0 * QK_STRIDE + k0 + tig + 4];
            uint32_t a3 = uQ[(r0 + 8) * QK_STRIDE + k0 + tig + 4];
#pragma unroll
            for (int na = 0; na < 8; na++) {
                uint32_t b0 = uK[(na * 8 + gid) * QK_STRIDE + k0 + tig];
                uint32_t b1 = uK[(na * 8 + gid) * QK_STRIDE + k0 + tig + 4];
                mma_tf32(accS[na][0], accS[na][1], accS[na][2], accS[na][3],
                         a0, a1, a2, a3, b0, b1);
            }
        }

        // ---- mask ----
#pragma unroll
        for (int na = 0; na < 8; na++) {
            int c0 = na * 8 + tig * 2;
            int sk0 = sSegK[c0], sk1 = sSegK[c0 + 1];
            if (sk0 != segq0) accS[na][0] = -1e30f;
            if (sk1 != segq0) accS[na][1] = -1e30f;
            if (sk0 != segq1) accS[na][2] = -1e30f;
            if (sk1 != segq1) accS[na][3] = -1e30f;
        }

        // ---- online softmax ----
        float mt0 = -1e30f, mt1 = -1e30f;
#pragma unroll
        for (int na = 0; na < 8; na++) {
            mt0 = fmaxf(mt0, fmaxf(accS[na][0], accS[na][1]));
            mt1 = fmaxf(mt1, fmaxf(accS[na][2], accS[na][3]));
        }
        mt0 = fmaxf(mt0, __shfl_xor_sync(0xffffffffu, mt0, 1));
        mt0 = fmaxf(mt0, __shfl_xor_sync(0xffffffffu, mt0, 2));
        mt1 = fmaxf(mt1, __shfl_xor_sync(0xffffffffu, mt1, 1));
        mt1 = fmaxf(mt1, __shfl_xor_sync(0xffffffffu, mt1, 2));
        float mn0 = fmaxf(m0, mt0);
        float mn1 = fmaxf(m1, mt1);

        float ls0 = 0.f, ls1 = 0.f;
#pragma unroll
        for (int na = 0; na < 8; na++) {
            float p00 = (accS[na][0] < -1e29f) ? 0.f : to_tf32(__expf(accS[na][0] - mn0));
            float p01 = (accS[na][1] < -1e29f) ? 0.f : to_tf32(__expf(accS[na][1] - mn0));
            float p10 = (accS[na][2] < -1e29f) ? 0.f : to_tf32(__expf(accS[na][2] - mn1));
            float p11 = (accS[na][3] < -1e29f) ? 0.f : to_tf32(__expf(accS[na][3] - mn1));
            ls0 += p00 + p01;
            ls1 += p10 + p11;
            int c0 = na * 8 + tig * 2;
            *(float2*)(&sP[r0 * P_STRIDE + c0]) = make_float2(p00, p01);
            *(float2*)(&sP[(r0 + 8) * P_STRIDE + c0]) = make_float2(p10, p11);
        }
        ls0 += __shfl_xor_sync(0xffffffffu, ls0, 1);
        ls0 += __shfl_xor_sync(0xffffffffu, ls0, 2);
        ls1 += __shfl_xor_sync(0xffffffffu, ls1, 1);
        ls1 += __shfl_xor_sync(0xffffffffu, ls1, 2);

        float al0 = __expf(m0 - mn0);
        float al1 = __expf(m1 - mn1);
        l0 = l0 * al0 + ls0;
        l1 = l1 * al1 + ls1;
        m0 = mn0; m1 = mn1;

#pragma unroll
        for (int no = 0; no < 9; no++) {
            O[no][0] *= al0; O[no][1] *= al0;
            O[no][2] *= al1; O[no][3] *= al1;
        }
        __syncwarp();

        // ---- O += P V ----
#pragma unroll
        for (int ks = 0; ks < 8; ks++) {
            const int k0 = ks * 8;
            uint32_t a0 = uP[r0 * P_STRIDE + k0 + tig];
            uint32_t a1 = uP[(r0 + 8) * P_STRIDE + k0 + tig];
            uint32_t a2 = uP[r0 * P_STRIDE + k0 + tig + 4];
            uint32_t a3 = uP[(r0 + 8) * P_STRIDE + k0 + tig + 4];
#pragma unroll
            for (int no = 0; no < 9; no++) {
                uint32_t b0 = uV[(k0 + tig) * V_STRIDE + no * 8 + gid];
                uint32_t b1 = uV[(k0 + tig + 4) * V_STRIDE + no * 8 + gid];
                mma_tf32(O[no][0], O[no][1], O[no][2], O[no][3],
                         a0, a1, a2, a3, b0, b1);
            }
        }
    }

    float il0 = 1.f / l0;
    float il1 = 1.f / l1;
    size_t ob0 = (size_t)(q0 + r0) * D_DIM + h * DH;
    size_t ob1 = (size_t)(q0 + r0 + 8) * D_DIM + h * DH;
#pragma unroll
    for (int no = 0; no < 9; no++) {
        int c0 = no * 8 + tig * 2;
        *(float2*)(out + ob0 + c0) = make_float2(to_tf32(O[no][0] * il0), to_tf32(O[no][1] * il0));
        *(float2*)(out + ob1 + c0) = make_float2(to_tf32(O[no][2] * il1), to_tf32(O[no][3] * il1));
    }
}

// ---------------- host launch ----------------
extern "C" void kernel_launch(void* const* d_in, const int* in_sizes, int n_in,
                              void* d_out, int out_size)
{
    const float* hs   = (const float*)d_in[0];
    const int*   cu   = (const int*)  d_in[1];
    const float* cosp = (const float*)d_in[2];
    const float* sinp = (const float*)d_in[3];
    const float* Wq   = (const float*)d_in[4];
    const float* bq   = (const float*)d_in[5];
    const float* Wk   = (const float*)d_in[6];
    const float* bk   = (const float*)d_in[7];
    const float* Wv   = (const float*)d_in[8];
    const float* bv   = (const float*)d_in[9];
    const float* Wo   = (const float*)d_in[10];
    const float* bo   = (const float*)d_in[11];
    float* out = (float*)d_out;

    float *part, *attn, *hsr, *wr, *qf, *kf, *vf;
    cudaGetSymbolAddress((void**)&part, g_part);
    cudaGetSymbolAddress((void**)&attn, g_attn);
    cudaGetSymbolAddress((void**)&hsr, g_hsr);
    cudaGetSymbolAddress((void**)&wr, g_wr);
    cudaGetSymbolAddress((void**)&qf, g_qf);
    cudaGetSymbolAddress((void**)&kf, g_kf);
    cudaGetSymbolAddress((void**)&vf, g_vf);
    float* wqr = wr;
    float* wkr = wr + (size_t)D_DIM * D_DIM;
    float* wvr = wr + 2 * (size_t)D_DIM * D_DIM;
    float* wor = wr + 3 * (size_t)D_DIM * D_DIM;

    // pre-round hs + weights (grid x sized for the LARGEST segment: hs)
    int n4hs = TD / 4;
    dim3 rgrid((n4hs + 255) / 256, 5);
    round_tf32_kernel<<<rgrid, 256>>>(hs, Wq, Wk, Wv, Wo);

    cudaFuncSetAttribute(gemm_cp_tf32,
                         cudaFuncAttributeMaxDynamicSharedMemorySize, GEMM_SMEM);

    // fused QKV, split-K x2: z = proj*2 + half -> g_part slots 0..5
    dim3 qkv_grid(D_DIM / BN, T_TOK / BM, 6);   // (9, 8, 6)
    gemm_cp_tf32<<<qkv_grid, 256, GEMM_SMEM>>>(hsr, wqr, wkr, wvr, part);

    // finalize q/k/v: partial sums + bias (+rope/scale), tf32-rounded
    dim3 fgrid((TD / 4 + 255) / 256, 2);
    finalize_qkv<<<fgrid, 256>>>(
        part + 0 * (size_t)TD, part + 1 * (size_t)TD,
        part + 2 * (size_t)TD, part + 3 * (size_t)TD,
        part + 4 * (size_t)TD, part + 5 * (size_t)TD,
        bq, bk, bv, cosp, sinp);

    // attention on finalized q/k/v (2 CTAs/SM, warp tile-skip)
    cudaFuncSetAttribute(attn_kernel,
                         cudaFuncAttributeMaxDynamicSharedMemorySize, ATTN_SMEM);
    attn_kernel<<<dim3(T_TOK / QT, H_NUM), 256, ATTN_SMEM>>>(qf, kf, vf, cu, attn);

    // O projection, split-K x2 -> slots 6,7
    dim3 o_grid(D_DIM / BN, T_TOK / BM, 2);     // (9, 8, 2)
    gemm_cp_tf32<<<o_grid, 256, GEMM_SMEM>>>(attn, wor, wor, wor, part + 6 * (size_t)TD);

    // final reduction: out = p6 + p7 + bo
    reduce_out_kernel<<<(TD / 4 + 255) / 256, 256>>>(
        part + 6 * (size_t)TD, part + 7 * (size_t)TD, bo, out);
}